// round 11
// baseline (speedup 1.0000x reference)
#include <cuda_runtime.h>
#include <cuda_fp16.h>
#include <math.h>
#include <cstdint>

#define BN 128
#define LN 105
#define MN 55
#define DN 256
#define ELN 3
static constexpr int BM = BN * MN;      // 7040
static constexpr int LL = LN * LN;      // 11025
static constexpr float SCALE = 0.0625f; // 1/sqrt(256)

// ---------------- scratch (device globals) ----------------
__device__ __align__(128) float g_xt[BM * LN];
__device__ __align__(128) __half g_zh[(size_t)BM * 35 * DN];       // fp16 Z
__device__ __align__(128) float g_wT[66048];                        // all branches
__device__ __align__(128) float g_meff[ELN * DN * DN];
__device__ __align__(128) uint4 g_bpack[ELN * 2 * 8 * 16 * 32];     // B fragments (384KB)
__device__ float g_u[ELN * DN];
__device__ float g_v[ELN * DN];
__device__ float g_cc[ELN];
__device__ __align__(128) float g_S[(size_t)ELN * BM * 35 * 35];

// ---------------- helpers ----------------
__device__ __forceinline__ uint32_t smem_u32(const void* p) {
    uint32_t a;
    asm("{ .reg .u64 t; cvta.to.shared.u64 t, %1; cvt.u32.u64 %0, t; }" : "=r"(a) : "l"(p));
    return a;
}
__device__ __forceinline__ void cp_async16(uint32_t saddr, const void* gptr) {
    asm volatile("cp.async.ca.shared.global [%0], [%1], 16;" :: "r"(saddr), "l"(gptr) : "memory");
}
__device__ __forceinline__ void mma16816(float* d, const uint32_t* a, uint32_t b0, uint32_t b1) {
    asm volatile(
        "mma.sync.aligned.m16n8k16.row.col.f32.f16.f16.f32 "
        "{%0,%1,%2,%3}, {%4,%5,%6,%7}, {%8,%9}, {%0,%1,%2,%3};"
        : "+f"(d[0]), "+f"(d[1]), "+f"(d[2]), "+f"(d[3])
        : "r"(a[0]), "r"(a[1]), "r"(a[2]), "r"(a[3]), "r"(b0), "r"(b1));
}
#define LDMX4(r0, r1, r2, r3, addr) \
    asm volatile("ldmatrix.sync.aligned.m8n8.x4.shared.b16 {%0,%1,%2,%3}, [%4];" \
        : "=r"(r0), "=r"(r1), "=r"(r2), "=r"(r3) : "r"(addr))

// ---------------- K1: revin + meff + uvc + wtrans(all branches) ----------------
__constant__ int c_wcum[7] = {0, 2304, 29184, 33024, 49152, 54528, 66048};
__constant__ int c_wC[6] = {3, 35, 5, 21, 7, 15};

__global__ __launch_bounds__(256) void k1_kernel(
    const float* __restrict__ x,
    const float* __restrict__ Wq, const float* __restrict__ Wk,
    const float* __restrict__ bq, const float* __restrict__ bk,
    const float* __restrict__ w0, const float* __restrict__ w1,
    const float* __restrict__ w2, const float* __restrict__ w3,
    const float* __restrict__ w4, const float* __restrict__ w5) {
    int blk = blockIdx.x;
    int tid = threadIdx.x;
    if (blk < 128) {
        __shared__ float sx[LN * MN];
        __shared__ float smean[MN], sinv[MN];
        int b = blk;
        const float* xb = x + (size_t)b * LN * MN;
        for (int i = tid; i < LN * MN; i += 256) sx[i] = xb[i];
        __syncthreads();
        for (int m = tid; m < MN; m += 256) {
            float s = 0.f, s2 = 0.f;
            for (int l = 0; l < LN; l++) { float v = sx[l * MN + m]; s += v; s2 += v * v; }
            float mean = s * (1.0f / LN);
            float var = s2 * (1.0f / LN) - mean * mean;
            smean[m] = mean;
            sinv[m] = rsqrtf(var + 1e-5f);
        }
        __syncthreads();
        float* ob = g_xt + (size_t)b * MN * LN;
        for (int i = tid; i < MN * LN; i += 256) {
            int m = i / LN, l = i - m * LN;
            ob[i] = (sx[l * MN + m] - smean[m]) * sinv[m];
        }
    } else if (blk < 896) {
        __shared__ float sq[16][17], sk[16][17];
        int u = blk - 128;
        int l = u >> 8;
        int rem = u & 255;
        int i0 = (rem >> 4) * 16, j0 = (rem & 15) * 16;
        int ty = tid >> 4, tx = tid & 15;
        float acc = 0.f;
        const float* wq = Wq + (size_t)l * DN * DN;
        const float* wk = Wk + (size_t)l * DN * DN;
        for (int k0 = 0; k0 < DN; k0 += 16) {
            sq[ty][tx] = wq[(i0 + ty) * DN + k0 + tx];
            sk[ty][tx] = wk[(j0 + ty) * DN + k0 + tx];
            __syncthreads();
#pragma unroll
            for (int kk = 0; kk < 16; kk++) acc += sq[ty][kk] * sk[tx][kk];
            __syncthreads();
        }
        g_meff[(size_t)l * DN * DN + (i0 + ty) * DN + j0 + tx] = acc;
    } else if (blk < 992) {
        int u = blk - 896;
        int l = u >> 5, r = u & 31;
        int wid = tid >> 5, lane = tid & 31;
        int k = r * 8 + wid;
        float su = 0.f, sv = 0.f;
        const float* wq = Wq + (size_t)l * DN * DN + (size_t)k * DN;
        const float* wk = Wk + (size_t)l * DN * DN + (size_t)k * DN;
        for (int d = lane; d < DN; d += 32) {
            su += wq[d] * bk[l * DN + d];
            sv += wk[d] * bq[l * DN + d];
        }
#pragma unroll
        for (int o = 16; o; o >>= 1) {
            su += __shfl_xor_sync(0xffffffffu, su, o);
            sv += __shfl_xor_sync(0xffffffffu, sv, o);
        }
        if (lane == 0) {
            g_u[l * DN + k] = su;
            g_v[l * DN + k] = sv;
        }
        if (r == 0 && wid == 0) {
            float c = 0.f;
            for (int d = lane; d < DN; d += 32) c += bq[l * DN + d] * bk[l * DN + d];
#pragma unroll
            for (int o = 16; o; o >>= 1) c += __shfl_xor_sync(0xffffffffu, c, o);
            if (lane == 0) g_cc[l] = c;
        }
    } else {
        int i = (blk - 992) * 256 + tid;
        if (i < 66048) {
            int br = 0;
#pragma unroll
            for (int q = 1; q < 6; q++)
                if (i >= c_wcum[q]) br = q;
            const float* wp = br == 0 ? w0 : br == 1 ? w1 : br == 2 ? w2 : br == 3 ? w3 : br == 4 ? w4 : w5;
            int j = i - c_wcum[br];
            int C3 = c_wC[br] * 3;
            int d = j / C3, r = j - d * C3;
            g_wT[c_wcum[br] + r * DN + d] = wp[j];
        }
    }
}

// ---------------- bpack: Meff^T -> mma fragment layout ----------------
// idx -> (l, h, tile, kstep, lane); uint4 = (b0,b1,b2,b3) fragments for
// n-tile base n0 = h*128 + tile*16, kstep*16.  B[n][k] = meff[k*256+n]
__global__ void bpack_kernel() {
    int idx = blockIdx.x * 256 + threadIdx.x;   // 0..24575
    int lane = idx & 31;
    int kstep = (idx >> 5) & 15;
    int tile = (idx >> 9) & 7;
    int h = (idx >> 12) & 1;
    int l = idx >> 13;
    int n0 = h * 128 + tile * 16 + (lane >> 2);
    int k0 = kstep * 16 + (lane & 3) * 2;
    const float* M = g_meff + (size_t)l * DN * DN;
    __half2 f0 = __floats2half2_rn(M[k0 * DN + n0], M[(k0 + 1) * DN + n0]);
    __half2 f1 = __floats2half2_rn(M[k0 * DN + n0 + 8], M[(k0 + 1) * DN + n0 + 8]);
    __half2 f2 = __floats2half2_rn(M[(k0 + 8) * DN + n0], M[(k0 + 9) * DN + n0]);
    __half2 f3 = __floats2half2_rn(M[(k0 + 8) * DN + n0 + 8], M[(k0 + 9) * DN + n0 + 8]);
    uint4 r;
    r.x = *(uint32_t*)&f0;
    r.y = *(uint32_t*)&f1;
    r.z = *(uint32_t*)&f2;
    r.w = *(uint32_t*)&f3;
    g_bpack[idx] = r;
}

// ---------------- circular conv + PE -> Z (fp16) ----------------
template <int T, int C>
__global__ __launch_bounds__(256) void conv_embed_kernel(int woff) {
    constexpr int CHUNK = 8;
    __shared__ float sx[LN];
    __shared__ float sw[3 * CHUNK * DN];
    int bm = blockIdx.x;
    int d = threadIdx.x;
    for (int i = threadIdx.x; i < LN; i += blockDim.x) sx[i] = g_xt[(size_t)bm * LN + i];
    float acc[T];
#pragma unroll
    for (int t = 0; t < T; t++) acc[t] = 0.f;
    const float* wT = g_wT + woff;
    for (int c0 = 0; c0 < C; c0 += CHUNK) {
        int cw = (C - c0 < CHUNK) ? (C - c0) : CHUNK;
        __syncthreads();
        for (int i = threadIdx.x; i < cw * 3 * DN; i += blockDim.x)
            sw[i] = wT[c0 * 3 * DN + i];
        __syncthreads();
        for (int ci = 0; ci < cw; ci++) {
            int c = c0 + ci;
            float w0 = sw[(ci * 3 + 0) * DN + d];
            float w1 = sw[(ci * 3 + 1) * DN + d];
            float w2 = sw[(ci * 3 + 2) * DN + d];
#pragma unroll
            for (int t = 0; t < T; t++) {
                int tm = (t == 0) ? (T - 1) : (t - 1);
                int tp = (t == T - 1) ? 0 : (t + 1);
                acc[t] += w0 * sx[tm * C + c] + w1 * sx[t * C + c] + w2 * sx[tp * C + c];
            }
        }
    }
    float freq = expf(-(float)(2 * (d >> 1)) * (9.210340371976184f / 256.f));
    bool isodd = (d & 1);
#pragma unroll
    for (int t = 0; t < T; t++) {
        float arg = (float)t * freq;
        float pe = isodd ? cosf(arg) : sinf(arg);
        g_zh[((size_t)bm * T + t) * DN + d] = __float2half_rn(acc[t] + pe);
    }
}

// ---------------- fused: all 3 layers, G = Zh@M, S = softmax(G Zh^T + bias) ----
static constexpr int OZH = 0;        // Zh [128][256] fp16 (65536)
static constexpr int OGH = 65536;    // G half [128][128] fp16 (32768)
static constexpr int OSS = 98304;    // S scratch (<= 18432)
static constexpr int OU  = 116736;   // u [3][256] f32 (3072)
static constexpr int OV  = 119808;   // v (3072)
static constexpr int OZU = 122880;   // zu [3][128] (1536)
static constexpr int OZV = 124416;   // zv (1536)
static constexpr int FUSED_SMEM = 125952;

template <int T>
__global__ __launch_bounds__(512, 1) void fused_kernel() {
    constexpr int MT = (T + 15) / 16;
    constexpr int QB = (T < 16) ? (16 / T) : 1;
    constexpr int NB = (T < 16) ? (8 * QB) : (128 / T);
    constexpr int NTILES = (T < 16) ? 8 : (NB * MT * MT);
    constexpr int TC = (T + 3) & ~3;
    constexpr int SLOTS = (NTILES + 15) / 16;

    extern __shared__ __align__(128) char smem[];
    const uint32_t sb = smem_u32(smem);
    const int tid = threadIdx.x;
    const int lane = tid & 31;
    const int wid = tid >> 5;
    const int bm0 = blockIdx.x * NB;
    const int nbm = min(NB, BM - bm0);
    const int nrows = nbm * T;

    // ---- load Z rows once (fp16), zero pad rows, stage u/v for all layers ----
    const __half* Zh = g_zh + (size_t)bm0 * T * DN;
    for (int idx = tid; idx < nrows * 32; idx += 512) {
        int r = idx >> 5, c = idx & 31;
        uint32_t off = r * 512 + ((c ^ (r & 7)) << 4);
        cp_async16(sb + OZH + off, Zh + (size_t)r * DN + c * 8);
    }
    asm volatile("cp.async.commit_group;" ::: "memory");
    for (int idx = tid + nrows * 32; idx < 128 * 32; idx += 512) {
        int r = idx >> 5, c = idx & 31;
        *(uint4*)(smem + OZH + r * 512 + (c << 4)) = make_uint4(0, 0, 0, 0);
    }
    for (int i = tid; i < 768; i += 512) {
        ((float*)(smem + OU))[i] = g_u[i];
        ((float*)(smem + OV))[i] = g_v[i];
    }
    asm volatile("cp.async.wait_group 0;" ::: "memory");
    __syncthreads();

    // ---- zu/zv per row for ALL 3 layers (4 threads per row, vectorized) ----
    {
        int r = tid >> 2, p = tid & 3;
        float au[3] = {0.f, 0.f, 0.f}, av[3] = {0.f, 0.f, 0.f};
        if (r < nrows) {
            const float4* su4 = (const float4*)(smem + OU);
            const float4* sv4 = (const float4*)(smem + OV);
            for (int c = p * 8; c < p * 8 + 8; c++) {
                uint32_t off = r * 512 + ((c ^ (r & 7)) << 4);
                uint4 zz = *(const uint4*)(smem + OZH + off);
                const __half2* hz = (const __half2*)&zz;
                float2 z0 = __half22float2(hz[0]);
                float2 z1 = __half22float2(hz[1]);
                float2 z2 = __half22float2(hz[2]);
                float2 z3 = __half22float2(hz[3]);
#pragma unroll
                for (int l = 0; l < 3; l++) {
                    int base = (l * DN + c * 8) >> 2;
                    float4 ua = su4[base], ub = su4[base + 1];
                    float4 va = sv4[base], vb = sv4[base + 1];
                    au[l] += z0.x * ua.x + z0.y * ua.y + z1.x * ua.z + z1.y * ua.w +
                             z2.x * ub.x + z2.y * ub.y + z3.x * ub.z + z3.y * ub.w;
                    av[l] += z0.x * va.x + z0.y * va.y + z1.x * va.z + z1.y * va.w +
                             z2.x * vb.x + z2.y * vb.y + z3.x * vb.z + z3.y * vb.w;
                }
            }
        }
#pragma unroll
        for (int l = 0; l < 3; l++) {
            au[l] += __shfl_xor_sync(0xffffffffu, au[l], 1);
            au[l] += __shfl_xor_sync(0xffffffffu, au[l], 2);
            av[l] += __shfl_xor_sync(0xffffffffu, av[l], 1);
            av[l] += __shfl_xor_sync(0xffffffffu, av[l], 2);
        }
        if (p == 0 && r < nrows) {
#pragma unroll
            for (int l = 0; l < 3; l++) {
                ((float*)(smem + OZU))[l * 128 + r] = au[l];
                ((float*)(smem + OZV))[l * 128 + r] = av[l];
            }
        }
    }

    const int wm = wid >> 2, wn = wid & 3;
    const int rA = lane & 15;
    const int chsel = lane >> 4;

    for (int layer = 0; layer < ELN; layer++) {
        __syncthreads();  // prior layer's softmax done reading sS/zu/zv

        float sfr[SLOTS][2][4];
#pragma unroll
        for (int s = 0; s < SLOTS; s++)
#pragma unroll
            for (int j = 0; j < 2; j++)
#pragma unroll
                for (int q = 0; q < 4; q++) sfr[s][j][q] = 0.f;

        for (int h = 0; h < 2; h++) {
            const uint4* Bp = g_bpack + ((size_t)(layer * 2 + h) * 8 * 16 * 32);
            float acc[2][4][4];
#pragma unroll
            for (int mt = 0; mt < 2; mt++)
#pragma unroll
                for (int j = 0; j < 4; j++)
#pragma unroll
                    for (int q = 0; q < 4; q++) acc[mt][j][q] = 0.f;

            // phase1: barrier-free (A from Z smem, B via LDG fragments)
#pragma unroll
            for (int kc = 0; kc < 4; kc++) {
#pragma unroll
                for (int ks = 0; ks < 4; ks++) {
                    int kstep = kc * 4 + ks;
                    int chA = kstep * 2 + chsel;
                    uint32_t ah[2][4];
#pragma unroll
                    for (int mt = 0; mt < 2; mt++) {
                        int row = wm * 32 + mt * 16 + rA;
                        uint32_t ad = sb + OZH + row * 512 + ((chA ^ (row & 7)) << 4);
                        LDMX4(ah[mt][0], ah[mt][1], ah[mt][2], ah[mt][3], ad);
                    }
#pragma unroll
                    for (int ng = 0; ng < 2; ng++) {
                        uint4 bb = __ldg(Bp + ((wn * 2 + ng) * 16 + kstep) * 32 + lane);
#pragma unroll
                        for (int mt = 0; mt < 2; mt++) {
                            mma16816(acc[mt][ng * 2 + 0], ah[mt], bb.x, bb.z);
                            mma16816(acc[mt][ng * 2 + 1], ah[mt], bb.y, bb.w);
                        }
                    }
                }
            }
            __syncthreads();   // prior phase2 done reading G before overwrite
            // G accum -> fp16 smem
#pragma unroll
            for (int mt = 0; mt < 2; mt++)
#pragma unroll
                for (int j = 0; j < 4; j++) {
                    int c = wn * 32 + (j >> 1) * 16 + (j & 1) * 8 + (lane & 3) * 2;
#pragma unroll
                    for (int half = 0; half < 2; half++) {
                        int r = wm * 32 + mt * 16 + (lane >> 2) + half * 8;
                        float v0 = acc[mt][j][half * 2 + 0];
                        float v1 = acc[mt][j][half * 2 + 1];
                        uint32_t off = r * 256 + ((((c >> 3)) ^ (r & 7)) << 4) + (c & 7) * 2;
                        *(__half2*)(smem + OGH + off) = __half2(__float2half_rn(v0), __float2half_rn(v1));
                    }
                }
            __syncthreads();
            // phase2: S += G @ Zh_half^T on diagonal tiles
            int slot = 0;
            for (int t = wid; t < NTILES; t += 16, slot++) {
                int rb, cb;
                if (T < 16) {
                    rb = cb = t * QB * T;
                } else {
                    int tbm = t / (MT * MT);
                    int rem = t % (MT * MT);
                    rb = tbm * T + (rem / MT) * 16;
                    cb = tbm * T + (rem % MT) * 16;
                }
#pragma unroll
                for (int kc = 0; kc < 8; kc++) {
                    int ch = kc * 2 + chsel;
                    int arow = rb + rA;
                    uint32_t aad = sb + OGH + arow * 256 + ((ch ^ (arow & 7)) << 4);
                    uint32_t gh[4];
                    LDMX4(gh[0], gh[1], gh[2], gh[3], aad);
                    int brow = cb + rA;
                    int chz = h * 16 + ch;
                    uint32_t bad = sb + OZH + brow * 512 + ((chz ^ (brow & 7)) << 4);
                    uint32_t zh2[4];
                    LDMX4(zh2[0], zh2[1], zh2[2], zh2[3], bad);
                    mma16816(sfr[slot][0], gh, zh2[0], zh2[2]);
                    mma16816(sfr[slot][1], gh, zh2[1], zh2[3]);
                }
            }
        }
        __syncthreads();

        // ---- S frags -> smem ----
        float* sS = (float*)(smem + OSS);
        {
            int slot = 0;
            for (int t = wid; t < NTILES; t += 16, slot++) {
                int tbm = -1, ti = 0, tj = 0;
                if (T >= 16) {
                    tbm = t / (MT * MT);
                    int rem = t % (MT * MT);
                    ti = rem / MT;
                    tj = rem % MT;
                }
                int fr = lane >> 2, fc = (lane & 3) * 2;
#pragma unroll
                for (int j = 0; j < 2; j++)
#pragma unroll
                    for (int q = 0; q < 4; q++) {
                        int rr = fr + (q >> 1) * 8;
                        int cc = fc + (q & 1) + j * 8;
                        float v = sfr[slot][j][q];
                        if (T < 16) {
                            int qr = rr / T, qc = cc / T;
                            if (qr == qc && qr < QB) {
                                int bm = t * QB + qr;
                                if (bm < nbm) sS[(bm * T + rr - qr * T) * TC + (cc - qc * T)] = v;
                            }
                        } else {
                            if (tbm < nbm && ti * 16 + rr < T && tj * 16 + cc < T)
                                sS[(tbm * T + ti * 16 + rr) * TC + tj * 16 + cc] = v;
                        }
                    }
            }
        }
        __syncthreads();

        // ---- softmax rows -> g_S ----
        float cterm = g_cc[layer];
        const float* zu = (const float*)(smem + OZU) + layer * 128;
        const float* zv = (const float*)(smem + OZV) + layer * 128;
        int e = lane;
        for (int rho = wid; rho < nrows; rho += 16) {
            int bm = rho / T, l = rho % T;
            const float* row = sS + (bm * T + l) * TC;
            bool v0 = (e < T);
            bool v1 = (T > 32) && (e + 32 < T);
            float zul = zu[rho];
            float x0 = v0 ? SCALE * (row[e] + zul + zv[bm * T + e] + cterm) : -1e30f;
            float x1 = v1 ? SCALE * (row[e + 32] + zul + zv[bm * T + e + 32] + cterm) : -1e30f;
            float mx = fmaxf(x0, x1);
#pragma unroll
            for (int o = 16; o; o >>= 1) mx = fmaxf(mx, __shfl_xor_sync(0xffffffffu, mx, o));
            float e0 = v0 ? __expf(x0 - mx) : 0.f;
            float e1 = v1 ? __expf(x1 - mx) : 0.f;
            float ssum = e0 + e1;
#pragma unroll
            for (int o = 16; o; o >>= 1) ssum += __shfl_xor_sync(0xffffffffu, ssum, o);
            float inv = 1.0f / ssum;
            float* So = g_S + ((size_t)layer * BM + bm0 + bm) * T * T + (size_t)l * T;
            if (v0) So[e] = e0 * inv;
            if (v1) So[e + 32] = e1 * inv;
        }
    }
}

// ---------------- channel mean + expand (fused) ----------------
template <int T, int P, bool TILE>
__global__ __launch_bounds__(256) void mean_expand_kernel(float* __restrict__ out) {
    constexpr int TT = T * T;
    __shared__ float sA[TT];
    int b = blockIdx.x, layer = blockIdx.y;
    const float* Sb = g_S + ((size_t)layer * BM + (size_t)b * MN) * TT;
    for (int r = threadIdx.x; r < TT; r += 256) {
        float s = 0.f;
#pragma unroll 5
        for (int m = 0; m < MN; m++) s += Sb[(size_t)m * TT + r];
        sA[r] = s * (1.0f / MN);
    }
    __syncthreads();
    float* ob = out + ((size_t)layer * BN + b) * LL;
    for (int i = threadIdx.x; i < LL; i += 256) {
        int l = i / LN, s = i - l * LN;
        int al = TILE ? (l % P) : (l / P);
        int as = TILE ? (s % P) : (s / P);
        ob[i] = sA[al * T + as];
    }
}

// ---------------- host orchestration ----------------
template <int T, int C, int P, bool TILE>
static void run_branch(int woff, float* outbase) {
    conv_embed_kernel<T, C><<<BM, 256>>>(woff);
    constexpr int QB = (T < 16) ? (16 / T) : 1;
    constexpr int NB = (T < 16) ? (8 * QB) : (128 / T);
    int nblk = (BM + NB - 1) / NB;
    cudaFuncSetAttribute(fused_kernel<T>, cudaFuncAttributeMaxDynamicSharedMemorySize, FUSED_SMEM);
    fused_kernel<T><<<nblk, 512, FUSED_SMEM>>>();
    mean_expand_kernel<T, P, TILE><<<dim3(BN, ELN), 256>>>(outbase);
}

extern "C" void kernel_launch(void* const* d_in, const int* in_sizes, int n_in,
                              void* d_out, int out_size) {
    const float* x = (const float*)d_in[0];
    const float* Wq = (const float*)d_in[7];
    const float* bq = (const float*)d_in[8];
    const float* Wk = (const float*)d_in[9];
    const float* bk = (const float*)d_in[10];
    float* out = (float*)d_out;

    k1_kernel<<<1250, 256>>>(x, Wq, Wk, bq, bk,
                             (const float*)d_in[1], (const float*)d_in[2],
                             (const float*)d_in[3], (const float*)d_in[4],
                             (const float*)d_in[5], (const float*)d_in[6]);
    bpack_kernel<<<96, 256>>>();

    run_branch<35, 3, 3, false>(0, out + (size_t)0 * BN * LL);
    run_branch<3, 35, 3, true>(2304, out + (size_t)9 * BN * LL);
    run_branch<21, 5, 5, false>(29184, out + (size_t)3 * BN * LL);
    run_branch<5, 21, 5, true>(33024, out + (size_t)12 * BN * LL);
    run_branch<15, 7, 7, false>(49152, out + (size_t)6 * BN * LL);
    run_branch<7, 15, 7, true>(54528, out + (size_t)15 * BN * LL);
}

// round 12
// speedup vs baseline: 1.0508x; 1.0508x over previous
#include <cuda_runtime.h>
#include <cuda_fp16.h>
#include <math.h>
#include <cstdint>

#define BN 128
#define LN 105
#define MN 55
#define DN 256
#define ELN 3
static constexpr int BM = BN * MN;      // 7040
static constexpr int LL = LN * LN;      // 11025
static constexpr float SCALE = 0.0625f; // 1/sqrt(256)

// ---------------- scratch (device globals) ----------------
__device__ __align__(128) float g_xt[BM * LN];
__device__ __align__(128) __half g_zh[(size_t)BM * 35 * DN];       // fp16 Z
__device__ __align__(128) float g_wT[66048];                        // all branches
__device__ __align__(128) float g_meff[ELN * DN * DN];
__device__ __align__(128) __half g_mth[ELN * DN * DN];              // MeffT [n][k] fp16
__device__ float g_u[ELN * DN];
__device__ float g_v[ELN * DN];
__device__ float g_cc[ELN];
__device__ __align__(128) float g_S[(size_t)ELN * BM * 35 * 35];

// ---------------- helpers ----------------
__device__ __forceinline__ uint32_t smem_u32(const void* p) {
    uint32_t a;
    asm("{ .reg .u64 t; cvta.to.shared.u64 t, %1; cvt.u32.u64 %0, t; }" : "=r"(a) : "l"(p));
    return a;
}
__device__ __forceinline__ void cp_async16(uint32_t saddr, const void* gptr) {
    asm volatile("cp.async.ca.shared.global [%0], [%1], 16;" :: "r"(saddr), "l"(gptr) : "memory");
}
__device__ __forceinline__ void mma16816(float* d, const uint32_t* a, uint32_t b0, uint32_t b1) {
    asm volatile(
        "mma.sync.aligned.m16n8k16.row.col.f32.f16.f16.f32 "
        "{%0,%1,%2,%3}, {%4,%5,%6,%7}, {%8,%9}, {%0,%1,%2,%3};"
        : "+f"(d[0]), "+f"(d[1]), "+f"(d[2]), "+f"(d[3])
        : "r"(a[0]), "r"(a[1]), "r"(a[2]), "r"(a[3]), "r"(b0), "r"(b1));
}
#define LDMX4(r0, r1, r2, r3, addr) \
    asm volatile("ldmatrix.sync.aligned.m8n8.x4.shared.b16 {%0,%1,%2,%3}, [%4];" \
        : "=r"(r0), "=r"(r1), "=r"(r2), "=r"(r3) : "r"(addr))

// ---------------- K1: revin + meff + uvc + wtrans(all branches) ----------------
__constant__ int c_wcum[7] = {0, 2304, 29184, 33024, 49152, 54528, 66048};
__constant__ int c_wC[6] = {3, 35, 5, 21, 7, 15};

__global__ __launch_bounds__(256) void k1_kernel(
    const float* __restrict__ x,
    const float* __restrict__ Wq, const float* __restrict__ Wk,
    const float* __restrict__ bq, const float* __restrict__ bk,
    const float* __restrict__ w0, const float* __restrict__ w1,
    const float* __restrict__ w2, const float* __restrict__ w3,
    const float* __restrict__ w4, const float* __restrict__ w5) {
    int blk = blockIdx.x;
    int tid = threadIdx.x;
    if (blk < 128) {
        __shared__ float sx[LN * MN];
        __shared__ float smean[MN], sinv[MN];
        int b = blk;
        const float* xb = x + (size_t)b * LN * MN;
        for (int i = tid; i < LN * MN; i += 256) sx[i] = xb[i];
        __syncthreads();
        for (int m = tid; m < MN; m += 256) {
            float s = 0.f, s2 = 0.f;
            for (int l = 0; l < LN; l++) { float v = sx[l * MN + m]; s += v; s2 += v * v; }
            float mean = s * (1.0f / LN);
            float var = s2 * (1.0f / LN) - mean * mean;
            smean[m] = mean;
            sinv[m] = rsqrtf(var + 1e-5f);
        }
        __syncthreads();
        float* ob = g_xt + (size_t)b * MN * LN;
        for (int i = tid; i < MN * LN; i += 256) {
            int m = i / LN, l = i - m * LN;
            ob[i] = (sx[l * MN + m] - smean[m]) * sinv[m];
        }
    } else if (blk < 896) {
        __shared__ float sq[16][17], sk[16][17];
        int u = blk - 128;
        int l = u >> 8;
        int rem = u & 255;
        int i0 = (rem >> 4) * 16, j0 = (rem & 15) * 16;
        int ty = tid >> 4, tx = tid & 15;
        float acc = 0.f;
        const float* wq = Wq + (size_t)l * DN * DN;
        const float* wk = Wk + (size_t)l * DN * DN;
        for (int k0 = 0; k0 < DN; k0 += 16) {
            sq[ty][tx] = wq[(i0 + ty) * DN + k0 + tx];
            sk[ty][tx] = wk[(j0 + ty) * DN + k0 + tx];
            __syncthreads();
#pragma unroll
            for (int kk = 0; kk < 16; kk++) acc += sq[ty][kk] * sk[tx][kk];
            __syncthreads();
        }
        g_meff[(size_t)l * DN * DN + (i0 + ty) * DN + j0 + tx] = acc;
    } else if (blk < 992) {
        int u = blk - 896;
        int l = u >> 5, r = u & 31;
        int wid = tid >> 5, lane = tid & 31;
        int k = r * 8 + wid;
        float su = 0.f, sv = 0.f;
        const float* wq = Wq + (size_t)l * DN * DN + (size_t)k * DN;
        const float* wk = Wk + (size_t)l * DN * DN + (size_t)k * DN;
        for (int d = lane; d < DN; d += 32) {
            su += wq[d] * bk[l * DN + d];
            sv += wk[d] * bq[l * DN + d];
        }
#pragma unroll
        for (int o = 16; o; o >>= 1) {
            su += __shfl_xor_sync(0xffffffffu, su, o);
            sv += __shfl_xor_sync(0xffffffffu, sv, o);
        }
        if (lane == 0) {
            g_u[l * DN + k] = su;
            g_v[l * DN + k] = sv;
        }
        if (r == 0 && wid == 0) {
            float c = 0.f;
            for (int d = lane; d < DN; d += 32) c += bq[l * DN + d] * bk[l * DN + d];
#pragma unroll
            for (int o = 16; o; o >>= 1) c += __shfl_xor_sync(0xffffffffu, c, o);
            if (lane == 0) g_cc[l] = c;
        }
    } else {
        int i = (blk - 992) * 256 + tid;
        if (i < 66048) {
            int br = 0;
#pragma unroll
            for (int q = 1; q < 6; q++)
                if (i >= c_wcum[q]) br = q;
            const float* wp = br == 0 ? w0 : br == 1 ? w1 : br == 2 ? w2 : br == 3 ? w3 : br == 4 ? w4 : w5;
            int j = i - c_wcum[br];
            int C3 = c_wC[br] * 3;
            int d = j / C3, r = j - d * C3;
            g_wT[c_wcum[br] + r * DN + d] = wp[j];
        }
    }
}

// ---------------- meffT: fp16 Meff^T ----------------
__global__ void meffT_kernel() {
    int l = blockIdx.y;
    int i = blockIdx.x * 256 + threadIdx.x;   // n*256+k
    int n = i >> 8, k = i & 255;
    float v = g_meff[(size_t)l * DN * DN + k * DN + n];
    g_mth[(size_t)l * DN * DN + i] = __float2half_rn(v);
}

// ---------------- circular conv + PE -> Z (fp16) ----------------
template <int T, int C>
__global__ __launch_bounds__(256) void conv_embed_kernel(int woff) {
    constexpr int CHUNK = 8;
    __shared__ float sx[LN];
    __shared__ float sw[3 * CHUNK * DN];
    int bm = blockIdx.x;
    int d = threadIdx.x;
    for (int i = threadIdx.x; i < LN; i += blockDim.x) sx[i] = g_xt[(size_t)bm * LN + i];
    float acc[T];
#pragma unroll
    for (int t = 0; t < T; t++) acc[t] = 0.f;
    const float* wT = g_wT + woff;
    for (int c0 = 0; c0 < C; c0 += CHUNK) {
        int cw = (C - c0 < CHUNK) ? (C - c0) : CHUNK;
        __syncthreads();
        for (int i = threadIdx.x; i < cw * 3 * DN; i += blockDim.x)
            sw[i] = wT[c0 * 3 * DN + i];
        __syncthreads();
        for (int ci = 0; ci < cw; ci++) {
            int c = c0 + ci;
            float w0 = sw[(ci * 3 + 0) * DN + d];
            float w1 = sw[(ci * 3 + 1) * DN + d];
            float w2 = sw[(ci * 3 + 2) * DN + d];
#pragma unroll
            for (int t = 0; t < T; t++) {
                int tm = (t == 0) ? (T - 1) : (t - 1);
                int tp = (t == T - 1) ? 0 : (t + 1);
                acc[t] += w0 * sx[tm * C + c] + w1 * sx[t * C + c] + w2 * sx[tp * C + c];
            }
        }
    }
    float freq = expf(-(float)(2 * (d >> 1)) * (9.210340371976184f / 256.f));
    bool isodd = (d & 1);
#pragma unroll
    for (int t = 0; t < T; t++) {
        float arg = (float)t * freq;
        float pe = isodd ? cosf(arg) : sinf(arg);
        g_zh[((size_t)bm * T + t) * DN + d] = __float2half_rn(acc[t] + pe);
    }
}

// ---------------- fused: all 3 layers, G = Zh@M, S = softmax(G Zh^T + bias) ----
static constexpr int OZH = 0;        // Zh [128][256] fp16 (65536)
static constexpr int OGH = 65536;    // G half [128][128] fp16 (32768)
static constexpr int OB0 = 98304;    // B buf0: [256 n][64 k] fp16 (32768)
static constexpr int OB1 = 131072;   // B buf1 (32768)
static constexpr int OSS = 98304;    // S overlay (reuses B0 region, <= 18432)
static constexpr int OU  = 163840;   // u [3][256] f32 (3072)
static constexpr int OV  = 166912;   // v (3072)
static constexpr int OZU = 169984;   // zu [3][128] (1536)
static constexpr int OZV = 171520;   // zv (1536)
static constexpr int FUSED_SMEM = 173056;

template <int T>
__global__ __launch_bounds__(512, 1) void fused_kernel() {
    constexpr int MT = (T + 15) / 16;
    constexpr int QB = (T < 16) ? (16 / T) : 1;
    constexpr int NB = (T < 16) ? (8 * QB) : (128 / T);
    constexpr int NTILES = (T < 16) ? 8 : (NB * MT * MT);
    constexpr int TC = (T + 3) & ~3;
    constexpr int SLOTS = (NTILES + 15) / 16;

    extern __shared__ __align__(128) char smem[];
    const uint32_t sb = smem_u32(smem);
    const int tid = threadIdx.x;
    const int lane = tid & 31;
    const int wid = tid >> 5;
    const int bm0 = blockIdx.x * NB;
    const int nbm = min(NB, BM - bm0);
    const int nrows = nbm * T;

    // ---- load Z rows once (fp16), zero pad rows, stage u/v for all layers ----
    const __half* Zh = g_zh + (size_t)bm0 * T * DN;
    for (int idx = tid; idx < nrows * 32; idx += 512) {
        int r = idx >> 5, c = idx & 31;
        uint32_t off = r * 512 + ((c ^ (r & 7)) << 4);
        cp_async16(sb + OZH + off, Zh + (size_t)r * DN + c * 8);
    }
    asm volatile("cp.async.commit_group;" ::: "memory");
    for (int idx = tid + nrows * 32; idx < 128 * 32; idx += 512) {
        int r = idx >> 5, c = idx & 31;
        *(uint4*)(smem + OZH + r * 512 + (c << 4)) = make_uint4(0, 0, 0, 0);
    }
    for (int i = tid; i < 768; i += 512) {
        ((float*)(smem + OU))[i] = g_u[i];
        ((float*)(smem + OV))[i] = g_v[i];
    }
    asm volatile("cp.async.wait_group 0;" ::: "memory");
    __syncthreads();

    // ---- zu/zv per row for ALL 3 layers (4 threads per row) ----
    {
        int r = tid >> 2, p = tid & 3;
        float au[3] = {0.f, 0.f, 0.f}, av[3] = {0.f, 0.f, 0.f};
        if (r < nrows) {
            const float4* su4 = (const float4*)(smem + OU);
            const float4* sv4 = (const float4*)(smem + OV);
            for (int c = p * 8; c < p * 8 + 8; c++) {
                uint32_t off = r * 512 + ((c ^ (r & 7)) << 4);
                uint4 zz = *(const uint4*)(smem + OZH + off);
                const __half2* hz = (const __half2*)&zz;
                float2 z0 = __half22float2(hz[0]);
                float2 z1 = __half22float2(hz[1]);
                float2 z2 = __half22float2(hz[2]);
                float2 z3 = __half22float2(hz[3]);
#pragma unroll
                for (int l = 0; l < 3; l++) {
                    int base = (l * DN + c * 8) >> 2;
                    float4 ua = su4[base], ub = su4[base + 1];
                    float4 va = sv4[base], vb = sv4[base + 1];
                    au[l] += z0.x * ua.x + z0.y * ua.y + z1.x * ua.z + z1.y * ua.w +
                             z2.x * ub.x + z2.y * ub.y + z3.x * ub.z + z3.y * ub.w;
                    av[l] += z0.x * va.x + z0.y * va.y + z1.x * va.z + z1.y * va.w +
                             z2.x * vb.x + z2.y * vb.y + z3.x * vb.z + z3.y * vb.w;
                }
            }
        }
#pragma unroll
        for (int l = 0; l < 3; l++) {
            au[l] += __shfl_xor_sync(0xffffffffu, au[l], 1);
            au[l] += __shfl_xor_sync(0xffffffffu, au[l], 2);
            av[l] += __shfl_xor_sync(0xffffffffu, av[l], 1);
            av[l] += __shfl_xor_sync(0xffffffffu, av[l], 2);
        }
        if (p == 0 && r < nrows) {
#pragma unroll
            for (int l = 0; l < 3; l++) {
                ((float*)(smem + OZU))[l * 128 + r] = au[l];
                ((float*)(smem + OZV))[l * 128 + r] = av[l];
            }
        }
    }

    const int wm = wid >> 2, wn = wid & 3;
    const int rA = lane & 15;
    const int chsel = lane >> 4;

// stage both n-halves of B (32KB: rows 0..255 = n) for k-chunk kc into buffer buf
#define STAGE_B(kc, buf)                                                            \
    do {                                                                            \
        uint32_t dst_ = sb + ((buf) ? OB1 : OB0);                                   \
        _Pragma("unroll")                                                           \
        for (int it_ = 0; it_ < 4; it_++) {                                         \
            int idx_ = it_ * 512 + tid;                                             \
            int row_ = idx_ >> 3, col_ = idx_ & 7;                                  \
            uint32_t off_ = row_ * 128 + ((col_ ^ (row_ & 7)) << 4);                \
            cp_async16(dst_ + off_, Bh_src + (size_t)row_ * DN + (kc) * 64 + col_ * 8); \
        }                                                                           \
        asm volatile("cp.async.commit_group;" ::: "memory");                        \
    } while (0)

    for (int layer = 0; layer < ELN; layer++) {
        __syncthreads();  // prior layer's softmax done reading sS (overlaid on B0)

        float sfr[SLOTS][2][4];
#pragma unroll
        for (int s = 0; s < SLOTS; s++)
#pragma unroll
            for (int j = 0; j < 2; j++)
#pragma unroll
                for (int q = 0; q < 4; q++) sfr[s][j][q] = 0.f;

        const __half* Bh_src = g_mth + (size_t)layer * DN * DN;

        float acc[2][2][4][4];
#pragma unroll
        for (int h = 0; h < 2; h++)
#pragma unroll
            for (int mt = 0; mt < 2; mt++)
#pragma unroll
                for (int j = 0; j < 4; j++)
#pragma unroll
                    for (int q = 0; q < 4; q++) acc[h][mt][j][q] = 0.f;

        // ---- phase1: single K pass, A loaded once, both n-halves accumulated ----
        STAGE_B(0, 0);
        for (int kc = 0; kc < 4; kc++) {
            asm volatile("cp.async.wait_group 0;" ::: "memory");
            __syncthreads();
            if (kc < 3) STAGE_B(kc + 1, (kc + 1) & 1);
            uint32_t sB = sb + ((kc & 1) ? OB1 : OB0);
#pragma unroll
            for (int ks = 0; ks < 4; ks++) {
                int chA = (kc * 4 + ks) * 2 + chsel;
                uint32_t ah[2][4];
#pragma unroll
                for (int mt = 0; mt < 2; mt++) {
                    int row = wm * 32 + mt * 16 + rA;
                    uint32_t ad = sb + OZH + row * 512 + ((chA ^ (row & 7)) << 4);
                    LDMX4(ah[mt][0], ah[mt][1], ah[mt][2], ah[mt][3], ad);
                }
#pragma unroll
                for (int h = 0; h < 2; h++) {
#pragma unroll
                    for (int ng = 0; ng < 2; ng++) {
                        int row = h * 128 + wn * 32 + ng * 16 + rA;
                        uint32_t bd = sB + row * 128 + (((ks * 2 + chsel) ^ (row & 7)) << 4);
                        uint32_t b0, b1, b2, b3;
                        LDMX4(b0, b1, b2, b3, bd);
#pragma unroll
                        for (int mt = 0; mt < 2; mt++) {
                            mma16816(acc[h][mt][ng * 2 + 0], ah[mt], b0, b2);
                            mma16816(acc[h][mt][ng * 2 + 1], ah[mt], b1, b3);
                        }
                    }
                }
            }
        }

        // ---- per half: G -> fp16 smem, then phase2 accumulate into sfr ----
        for (int h = 0; h < 2; h++) {
            __syncthreads();   // previous phase2 (or previous layer) done with OGH
#pragma unroll
            for (int mt = 0; mt < 2; mt++)
#pragma unroll
                for (int j = 0; j < 4; j++) {
                    int c = wn * 32 + (j >> 1) * 16 + (j & 1) * 8 + (lane & 3) * 2;
#pragma unroll
                    for (int half = 0; half < 2; half++) {
                        int r = wm * 32 + mt * 16 + (lane >> 2) + half * 8;
                        float v0 = acc[h][mt][j][half * 2 + 0];
                        float v1 = acc[h][mt][j][half * 2 + 1];
                        uint32_t off = r * 256 + ((((c >> 3)) ^ (r & 7)) << 4) + (c & 7) * 2;
                        *(__half2*)(smem + OGH + off) = __half2(__float2half_rn(v0), __float2half_rn(v1));
                    }
                }
            __syncthreads();
            int slot = 0;
            for (int t = wid; t < NTILES; t += 16, slot++) {
                int rb, cb;
                if (T < 16) {
                    rb = cb = t * QB * T;
                } else {
                    int tbm = t / (MT * MT);
                    int rem = t % (MT * MT);
                    rb = tbm * T + (rem / MT) * 16;
                    cb = tbm * T + (rem % MT) * 16;
                }
#pragma unroll
                for (int kc = 0; kc < 8; kc++) {
                    int ch = kc * 2 + chsel;
                    int arow = rb + rA;
                    uint32_t aad = sb + OGH + arow * 256 + ((ch ^ (arow & 7)) << 4);
                    uint32_t gh[4];
                    LDMX4(gh[0], gh[1], gh[2], gh[3], aad);
                    int brow = cb + rA;
                    int chz = h * 16 + ch;
                    uint32_t bad = sb + OZH + brow * 512 + ((chz ^ (brow & 7)) << 4);
                    uint32_t zh2[4];
                    LDMX4(zh2[0], zh2[1], zh2[2], zh2[3], bad);
                    mma16816(sfr[slot][0], gh, zh2[0], zh2[2]);
                    mma16816(sfr[slot][1], gh, zh2[1], zh2[3]);
                }
            }
        }
        __syncthreads();

        // ---- S frags -> smem overlay ----
        float* sS = (float*)(smem + OSS);
        {
            int slot = 0;
            for (int t = wid; t < NTILES; t += 16, slot++) {
                int tbm = -1, ti = 0, tj = 0;
                if (T >= 16) {
                    tbm = t / (MT * MT);
                    int rem = t % (MT * MT);
                    ti = rem / MT;
                    tj = rem % MT;
                }
                int fr = lane >> 2, fc = (lane & 3) * 2;
#pragma unroll
                for (int j = 0; j < 2; j++)
#pragma unroll
                    for (int q = 0; q < 4; q++) {
                        int rr = fr + (q >> 1) * 8;
                        int cc = fc + (q & 1) + j * 8;
                        float v = sfr[slot][j][q];
                        if (T < 16) {
                            int qr = rr / T, qc = cc / T;
                            if (qr == qc && qr < QB) {
                                int bm = t * QB + qr;
                                if (bm < nbm) sS[(bm * T + rr - qr * T) * TC + (cc - qc * T)] = v;
                            }
                        } else {
                            if (tbm < nbm && ti * 16 + rr < T && tj * 16 + cc < T)
                                sS[(tbm * T + ti * 16 + rr) * TC + tj * 16 + cc] = v;
                        }
                    }
            }
        }
        __syncthreads();

        // ---- softmax rows -> g_S ----
        float cterm = g_cc[layer];
        const float* zu = (const float*)(smem + OZU) + layer * 128;
        const float* zv = (const float*)(smem + OZV) + layer * 128;
        int e = lane;
        for (int rho = wid; rho < nrows; rho += 16) {
            int bm = rho / T, l = rho % T;
            const float* row = sS + (bm * T + l) * TC;
            bool v0 = (e < T);
            bool v1 = (T > 32) && (e + 32 < T);
            float zul = zu[rho];
            float x0 = v0 ? SCALE * (row[e] + zul + zv[bm * T + e] + cterm) : -1e30f;
            float x1 = v1 ? SCALE * (row[e + 32] + zul + zv[bm * T + e + 32] + cterm) : -1e30f;
            float mx = fmaxf(x0, x1);
#pragma unroll
            for (int o = 16; o; o >>= 1) mx = fmaxf(mx, __shfl_xor_sync(0xffffffffu, mx, o));
            float e0 = v0 ? __expf(x0 - mx) : 0.f;
            float e1 = v1 ? __expf(x1 - mx) : 0.f;
            float ssum = e0 + e1;
#pragma unroll
            for (int o = 16; o; o >>= 1) ssum += __shfl_xor_sync(0xffffffffu, ssum, o);
            float inv = 1.0f / ssum;
            float* So = g_S + ((size_t)layer * BM + bm0 + bm) * T * T + (size_t)l * T;
            if (v0) So[e] = e0 * inv;
            if (v1) So[e + 32] = e1 * inv;
        }
    }
#undef STAGE_B
}

// ---------------- channel mean + expand (fused) ----------------
template <int T, int P, bool TILE>
__global__ __launch_bounds__(256) void mean_expand_kernel(float* __restrict__ out) {
    constexpr int TT = T * T;
    __shared__ float sA[TT];
    int b = blockIdx.x, layer = blockIdx.y;
    const float* Sb = g_S + ((size_t)layer * BM + (size_t)b * MN) * TT;
    for (int r = threadIdx.x; r < TT; r += 256) {
        float s = 0.f;
#pragma unroll 5
        for (int m = 0; m < MN; m++) s += Sb[(size_t)m * TT + r];
        sA[r] = s * (1.0f / MN);
    }
    __syncthreads();
    float* ob = out + ((size_t)layer * BN + b) * LL;
    for (int i = threadIdx.x; i < LL; i += 256) {
        int l = i / LN, s = i - l * LN;
        int al = TILE ? (l % P) : (l / P);
        int as = TILE ? (s % P) : (s / P);
        ob[i] = sA[al * T + as];
    }
}

// ---------------- host orchestration ----------------
template <int T, int C, int P, bool TILE>
static void run_branch(int woff, float* outbase) {
    conv_embed_kernel<T, C><<<BM, 256>>>(woff);
    constexpr int QB = (T < 16) ? (16 / T) : 1;
    constexpr int NB = (T < 16) ? (8 * QB) : (128 / T);
    int nblk = (BM + NB - 1) / NB;
    cudaFuncSetAttribute(fused_kernel<T>, cudaFuncAttributeMaxDynamicSharedMemorySize, FUSED_SMEM);
    fused_kernel<T><<<nblk, 512, FUSED_SMEM>>>();
    mean_expand_kernel<T, P, TILE><<<dim3(BN, ELN), 256>>>(outbase);
}

extern "C" void kernel_launch(void* const* d_in, const int* in_sizes, int n_in,
                              void* d_out, int out_size) {
    const float* x = (const float*)d_in[0];
    const float* Wq = (const float*)d_in[7];
    const float* bq = (const float*)d_in[8];
    const float* Wk = (const float*)d_in[9];
    const float* bk = (const float*)d_in[10];
    float* out = (float*)d_out;

    k1_kernel<<<1250, 256>>>(x, Wq, Wk, bq, bk,
                             (const float*)d_in[1], (const float*)d_in[2],
                             (const float*)d_in[3], (const float*)d_in[4],
                             (const float*)d_in[5], (const float*)d_in[6]);
    meffT_kernel<<<dim3(256, ELN), 256>>>();

    run_branch<35, 3, 3, false>(0, out + (size_t)0 * BN * LL);
    run_branch<3, 35, 3, true>(2304, out + (size_t)9 * BN * LL);
    run_branch<21, 5, 5, false>(29184, out + (size_t)3 * BN * LL);
    run_branch<5, 21, 5, true>(33024, out + (size_t)12 * BN * LL);
    run_branch<15, 7, 7, false>(49152, out + (size_t)6 * BN * LL);
    run_branch<7, 15, 7, true>(54528, out + (size_t)15 * BN * LL);
}

// round 13
// speedup vs baseline: 1.3017x; 1.2388x over previous
#include <cuda_runtime.h>
#include <cuda_fp16.h>
#include <math.h>
#include <cstdint>

#define BN 128
#define LN 105
#define MN 55
#define DN 256
#define ELN 3
static constexpr int BM = BN * MN;      // 7040
static constexpr int LL = LN * LN;      // 11025
static constexpr float SCALE = 0.0625f; // 1/sqrt(256)

// ---------------- scratch (device globals) ----------------
__device__ __align__(128) float g_xt[BM * LN];
__device__ __align__(128) float g_meff[ELN * DN * DN];
__device__ __align__(128) __half g_mth[ELN * DN * DN];    // MeffT [n][k] fp16
__device__ __align__(128) __half g_wth[6 * DN * DN];      // conv W [br][d][k<=255] fp16, zero-padded
__device__ __align__(128) float g_pe[86 * DN];            // PE tables (T=35,3,21,5,15,7)
__device__ float g_u[ELN * DN];
__device__ float g_v[ELN * DN];
__device__ float g_cc[ELN];
__device__ __align__(128) float g_S[(size_t)ELN * BM * 35 * 35];

// ---------------- helpers ----------------
__device__ __forceinline__ uint32_t smem_u32(const void* p) {
    uint32_t a;
    asm("{ .reg .u64 t; cvta.to.shared.u64 t, %1; cvt.u32.u64 %0, t; }" : "=r"(a) : "l"(p));
    return a;
}
__device__ __forceinline__ void cp_async16(uint32_t saddr, const void* gptr) {
    asm volatile("cp.async.ca.shared.global [%0], [%1], 16;" :: "r"(saddr), "l"(gptr) : "memory");
}
__device__ __forceinline__ void mma16816(float* d, const uint32_t* a, uint32_t b0, uint32_t b1) {
    asm volatile(
        "mma.sync.aligned.m16n8k16.row.col.f32.f16.f16.f32 "
        "{%0,%1,%2,%3}, {%4,%5,%6,%7}, {%8,%9}, {%0,%1,%2,%3};"
        : "+f"(d[0]), "+f"(d[1]), "+f"(d[2]), "+f"(d[3])
        : "r"(a[0]), "r"(a[1]), "r"(a[2]), "r"(a[3]), "r"(b0), "r"(b1));
}
#define LDMX4(r0, r1, r2, r3, addr) \
    asm volatile("ldmatrix.sync.aligned.m8n8.x4.shared.b16 {%0,%1,%2,%3}, [%4];" \
        : "=r"(r0), "=r"(r1), "=r"(r2), "=r"(r3) : "r"(addr))

// ---------------- K1: revin + meff + uvc + wth + pe ----------------
__constant__ int c_wC[6] = {3, 35, 5, 21, 7, 15};    // C per branch
__constant__ int c_peT[6] = {35, 3, 21, 5, 15, 7};   // T per branch
__constant__ int c_peS[7] = {0, 35, 38, 59, 64, 79, 86};

__global__ __launch_bounds__(256) void k1_kernel(
    const float* __restrict__ x,
    const float* __restrict__ Wq, const float* __restrict__ Wk,
    const float* __restrict__ bq, const float* __restrict__ bk,
    const float* __restrict__ w0, const float* __restrict__ w1,
    const float* __restrict__ w2, const float* __restrict__ w3,
    const float* __restrict__ w4, const float* __restrict__ w5) {
    int blk = blockIdx.x;
    int tid = threadIdx.x;
    if (blk < 128) {
        __shared__ float sx[LN * MN];
        __shared__ float smean[MN], sinv[MN];
        int b = blk;
        const float* xb = x + (size_t)b * LN * MN;
        for (int i = tid; i < LN * MN; i += 256) sx[i] = xb[i];
        __syncthreads();
        for (int m = tid; m < MN; m += 256) {
            float s = 0.f, s2 = 0.f;
            for (int l = 0; l < LN; l++) { float v = sx[l * MN + m]; s += v; s2 += v * v; }
            float mean = s * (1.0f / LN);
            float var = s2 * (1.0f / LN) - mean * mean;
            smean[m] = mean;
            sinv[m] = rsqrtf(var + 1e-5f);
        }
        __syncthreads();
        float* ob = g_xt + (size_t)b * MN * LN;
        for (int i = tid; i < MN * LN; i += 256) {
            int m = i / LN, l = i - m * LN;
            ob[i] = (sx[l * MN + m] - smean[m]) * sinv[m];
        }
    } else if (blk < 896) {
        __shared__ float sq[16][17], sk[16][17];
        int u = blk - 128;
        int l = u >> 8;
        int rem = u & 255;
        int i0 = (rem >> 4) * 16, j0 = (rem & 15) * 16;
        int ty = tid >> 4, tx = tid & 15;
        float acc = 0.f;
        const float* wq = Wq + (size_t)l * DN * DN;
        const float* wk = Wk + (size_t)l * DN * DN;
        for (int k0 = 0; k0 < DN; k0 += 16) {
            sq[ty][tx] = wq[(i0 + ty) * DN + k0 + tx];
            sk[ty][tx] = wk[(j0 + ty) * DN + k0 + tx];
            __syncthreads();
#pragma unroll
            for (int kk = 0; kk < 16; kk++) acc += sq[ty][kk] * sk[tx][kk];
            __syncthreads();
        }
        g_meff[(size_t)l * DN * DN + (i0 + ty) * DN + j0 + tx] = acc;
    } else if (blk < 992) {
        int u = blk - 896;
        int l = u >> 5, r = u & 31;
        int wid = tid >> 5, lane = tid & 31;
        int k = r * 8 + wid;
        float su = 0.f, sv = 0.f;
        const float* wq = Wq + (size_t)l * DN * DN + (size_t)k * DN;
        const float* wk = Wk + (size_t)l * DN * DN + (size_t)k * DN;
        for (int d = lane; d < DN; d += 32) {
            su += wq[d] * bk[l * DN + d];
            sv += wk[d] * bq[l * DN + d];
        }
#pragma unroll
        for (int o = 16; o; o >>= 1) {
            su += __shfl_xor_sync(0xffffffffu, su, o);
            sv += __shfl_xor_sync(0xffffffffu, sv, o);
        }
        if (lane == 0) {
            g_u[l * DN + k] = su;
            g_v[l * DN + k] = sv;
        }
        if (r == 0 && wid == 0) {
            float c = 0.f;
            for (int d = lane; d < DN; d += 32) c += bq[l * DN + d] * bk[l * DN + d];
#pragma unroll
            for (int o = 16; o; o >>= 1) c += __shfl_xor_sync(0xffffffffu, c, o);
            if (lane == 0) g_cc[l] = c;
        }
    } else if (blk < 2528) {
        // ---- wth: conv weights -> fp16, zero-padded to [256][256], k = c*3+j ----
        int idx = (blk - 992) * 256 + tid;
        int br = idx >> 16;
        int rem = idx & 65535;
        int d = rem >> 8, k = rem & 255;
        int C3 = c_wC[br] * 3;
        const float* wp = br == 0 ? w0 : br == 1 ? w1 : br == 2 ? w2 : br == 3 ? w3 : br == 4 ? w4 : w5;
        float v = (k < C3) ? wp[d * C3 + k] : 0.f;
        g_wth[idx] = __float2half_rn(v);
    } else {
        // ---- pe tables ----
        int tg = blk - 2528;   // 0..85
        int d = tid;
        int seg = 0;
#pragma unroll
        for (int q = 1; q < 6; q++)
            if (tg >= c_peS[q]) seg = q;
        int t = tg - c_peS[seg];
        float freq = expf(-(float)(2 * (d >> 1)) * (9.210340371976184f / 256.f));
        float arg = (float)t * freq;
        g_pe[tg * DN + d] = (d & 1) ? cosf(arg) : sinf(arg);
    }
}

// ---------------- meffT: fp16 Meff^T ----------------
__global__ void meffT_kernel() {
    int l = blockIdx.y;
    int i = blockIdx.x * 256 + threadIdx.x;   // n*256+k
    int n = i >> 8, k = i & 255;
    float v = g_meff[(size_t)l * DN * DN + k * DN + n];
    g_mth[(size_t)l * DN * DN + i] = __float2half_rn(v);
}

// ---------------- fused: conv->Z, then 3 layers: G = Z@M, S = softmax(...) ----
static constexpr int OZH = 0;        // Zh [128][256] fp16 (65536)
static constexpr int OGH = 65536;    // G / Xwin [128][128] fp16 (32768)
static constexpr int OB0 = 98304;    // B buf0: [256 n][64 k] fp16 (32768)
static constexpr int OB1 = 131072;   // B buf1 (32768)
static constexpr int OSS = 98304;    // S overlay (reuses B0 region)
static constexpr int OU  = 163840;   // u [3][256] f32 (3072)
static constexpr int OV  = 166912;   // v (3072)
static constexpr int OZU = 169984;   // zu [3][128] (1536)
static constexpr int OZV = 171520;   // zv (1536)
static constexpr int FUSED_SMEM = 173056;

template <int T, int C>
__global__ __launch_bounds__(512, 1) void fused_kernel(int br, int peoff) {
    constexpr int MT = (T + 15) / 16;
    constexpr int QB = (T < 16) ? (16 / T) : 1;
    constexpr int NB = (T < 16) ? (8 * QB) : (128 / T);
    constexpr int NTILES = (T < 16) ? 8 : (NB * MT * MT);
    constexpr int TC = (T + 3) & ~3;
    constexpr int TCS = TC + 1;
    constexpr int SLOTS = (NTILES + 15) / 16;
    constexpr int KST = (3 * C + 15) / 16;   // conv k-steps
    constexpr int NCH = (3 * C + 63) / 64;   // conv 64k chunks (1 or 2)

    extern __shared__ __align__(128) char smem[];
    const uint32_t sb = smem_u32(smem);
    const int tid = threadIdx.x;
    const int lane = tid & 31;
    const int wid = tid >> 5;
    const int bm0 = blockIdx.x * NB;
    const int nbm = min(NB, BM - bm0);
    const int nrows = nbm * T;

    const int wm = wid >> 2, wn = wid & 3;
    const int rA = lane & 15;
    const int chsel = lane >> 4;

    // ---- stage u/v ----
    for (int i = tid; i < 768; i += 512) {
        ((float*)(smem + OU))[i] = g_u[i];
        ((float*)(smem + OV))[i] = g_v[i];
    }

    // ---- build Xwin (im2col of circular conv) in OGH region, fp16 [128][128] ----
    for (int i = tid; i < 128 * 128; i += 512) {
        int r = i >> 7, k = i & 127;
        float v = 0.f;
        if (r < nrows && k < 3 * C) {
            int bmi = r / T, t = r - (r / T) * T;
            int c = k / 3, j = k - c * 3;
            int ts = t + j - 1;
            ts = (ts < 0) ? ts + T : (ts >= T ? ts - T : ts);
            v = __ldg(&g_xt[(size_t)(bm0 + bmi) * LN + ts * C + c]);
        }
        uint32_t off = r * 256 + (((k >> 3) ^ (r & 7)) << 4) + (k & 7) * 2;
        *(__half*)(smem + OGH + off) = __float2half_rn(v);
    }

    // ---- stage conv weights (1 or 2 chunks of [256][64]) ----
    {
        const __half* Wsrc = g_wth + (size_t)br * DN * DN;
#pragma unroll
        for (int ch = 0; ch < NCH; ch++) {
            uint32_t dst = sb + (ch ? OB1 : OB0);
#pragma unroll
            for (int it = 0; it < 4; it++) {
                int idx = it * 512 + tid;
                int row = idx >> 3, col = idx & 7;
                uint32_t off = row * 128 + ((col ^ (row & 7)) << 4);
                cp_async16(dst + off, Wsrc + (size_t)row * DN + ch * 64 + col * 8);
            }
        }
        asm volatile("cp.async.commit_group;" ::: "memory");
    }
    asm volatile("cp.async.wait_group 0;" ::: "memory");
    __syncthreads();

    // ---- conv GEMM: Z = Xwin @ W^T (+PE) ----
    {
        float acc[2][2][4][4];
#pragma unroll
        for (int h = 0; h < 2; h++)
#pragma unroll
            for (int mt = 0; mt < 2; mt++)
#pragma unroll
                for (int j = 0; j < 4; j++)
#pragma unroll
                    for (int q = 0; q < 4; q++) acc[h][mt][j][q] = 0.f;

#pragma unroll
        for (int kstep = 0; kstep < KST; kstep++) {
            int buf = kstep >> 2, ksl = kstep & 3;
            uint32_t sB = sb + (buf ? OB1 : OB0);
            int chA = kstep * 2 + chsel;
            uint32_t ah[2][4];
#pragma unroll
            for (int mt = 0; mt < 2; mt++) {
                int row = wm * 32 + mt * 16 + rA;
                uint32_t ad = sb + OGH + row * 256 + ((chA ^ (row & 7)) << 4);
                LDMX4(ah[mt][0], ah[mt][1], ah[mt][2], ah[mt][3], ad);
            }
#pragma unroll
            for (int h = 0; h < 2; h++) {
#pragma unroll
                for (int ng = 0; ng < 2; ng++) {
                    int row = h * 128 + wn * 32 + ng * 16 + rA;
                    uint32_t bd = sB + row * 128 + (((ksl * 2 + chsel) ^ (row & 7)) << 4);
                    uint32_t b0, b1, b2, b3;
                    LDMX4(b0, b1, b2, b3, bd);
#pragma unroll
                    for (int mt = 0; mt < 2; mt++) {
                        mma16816(acc[h][mt][ng * 2 + 0], ah[mt], b0, b2);
                        mma16816(acc[h][mt][ng * 2 + 1], ah[mt], b1, b3);
                    }
                }
            }
        }
        // epilogue: Z = acc + PE (zero for pad rows), write to OZH
        const float* peb = g_pe + (size_t)peoff * DN;
#pragma unroll
        for (int h = 0; h < 2; h++)
#pragma unroll
            for (int mt = 0; mt < 2; mt++)
#pragma unroll
                for (int j = 0; j < 4; j++) {
                    int c = h * 128 + wn * 32 + (j >> 1) * 16 + (j & 1) * 8 + (lane & 3) * 2;
#pragma unroll
                    for (int half = 0; half < 2; half++) {
                        int r = wm * 32 + mt * 16 + (lane >> 2) + half * 8;
                        __half2 hv;
                        if (r < nrows) {
                            int t = r - (r / T) * T;
                            float2 pe = __ldg((const float2*)(peb + t * DN + c));
                            hv = __half2(__float2half_rn(acc[h][mt][j][half * 2 + 0] + pe.x),
                                         __float2half_rn(acc[h][mt][j][half * 2 + 1] + pe.y));
                        } else {
                            hv = __half2(__float2half_rn(0.f), __float2half_rn(0.f));
                        }
                        uint32_t off = r * 512 + ((((c >> 3)) ^ (r & 7)) << 4) + (c & 7) * 2;
                        *(__half2*)(smem + OZH + off) = hv;
                    }
                }
    }
    __syncthreads();

    // ---- zu/zv per row for ALL 3 layers (4 threads per row) ----
    {
        int r = tid >> 2, p = tid & 3;
        float au[3] = {0.f, 0.f, 0.f}, av[3] = {0.f, 0.f, 0.f};
        if (r < nrows) {
            const float4* su4 = (const float4*)(smem + OU);
            const float4* sv4 = (const float4*)(smem + OV);
            for (int c = p * 8; c < p * 8 + 8; c++) {
                uint32_t off = r * 512 + ((c ^ (r & 7)) << 4);
                uint4 zz = *(const uint4*)(smem + OZH + off);
                const __half2* hz = (const __half2*)&zz;
                float2 z0 = __half22float2(hz[0]);
                float2 z1 = __half22float2(hz[1]);
                float2 z2 = __half22float2(hz[2]);
                float2 z3 = __half22float2(hz[3]);
#pragma unroll
                for (int l = 0; l < 3; l++) {
                    int base = (l * DN + c * 8) >> 2;
                    float4 ua = su4[base], ub = su4[base + 1];
                    float4 va = sv4[base], vb = sv4[base + 1];
                    au[l] += z0.x * ua.x + z0.y * ua.y + z1.x * ua.z + z1.y * ua.w +
                             z2.x * ub.x + z2.y * ub.y + z3.x * ub.z + z3.y * ub.w;
                    av[l] += z0.x * va.x + z0.y * va.y + z1.x * va.z + z1.y * va.w +
                             z2.x * vb.x + z2.y * vb.y + z3.x * vb.z + z3.y * vb.w;
                }
            }
        }
#pragma unroll
        for (int l = 0; l < 3; l++) {
            au[l] += __shfl_xor_sync(0xffffffffu, au[l], 1);
            au[l] += __shfl_xor_sync(0xffffffffu, au[l], 2);
            av[l] += __shfl_xor_sync(0xffffffffu, av[l], 1);
            av[l] += __shfl_xor_sync(0xffffffffu, av[l], 2);
        }
        if (p == 0 && r < nrows) {
#pragma unroll
            for (int l = 0; l < 3; l++) {
                ((float*)(smem + OZU))[l * 128 + r] = au[l];
                ((float*)(smem + OZV))[l * 128 + r] = av[l];
            }
        }
    }

// stage both n-halves of B for k-chunk kc into buffer buf
#define STAGE_B(kc, buf)                                                            \
    do {                                                                            \
        uint32_t dst_ = sb + ((buf) ? OB1 : OB0);                                   \
        _Pragma("unroll")                                                           \
        for (int it_ = 0; it_ < 4; it_++) {                                         \
            int idx_ = it_ * 512 + tid;                                             \
            int row_ = idx_ >> 3, col_ = idx_ & 7;                                  \
            uint32_t off_ = row_ * 128 + ((col_ ^ (row_ & 7)) << 4);                \
            cp_async16(dst_ + off_, Bh_src + (size_t)row_ * DN + (kc) * 64 + col_ * 8); \
        }                                                                           \
        asm volatile("cp.async.commit_group;" ::: "memory");                        \
    } while (0)

    for (int layer = 0; layer < ELN; layer++) {
        __syncthreads();  // prior layer's softmax done reading sS (overlaid on B0)

        float sfr[SLOTS][2][4];
#pragma unroll
        for (int s = 0; s < SLOTS; s++)
#pragma unroll
            for (int j = 0; j < 2; j++)
#pragma unroll
                for (int q = 0; q < 4; q++) sfr[s][j][q] = 0.f;

        const __half* Bh_src = g_mth + (size_t)layer * DN * DN;

        float acc[2][2][4][4];
#pragma unroll
        for (int h = 0; h < 2; h++)
#pragma unroll
            for (int mt = 0; mt < 2; mt++)
#pragma unroll
                for (int j = 0; j < 4; j++)
#pragma unroll
                    for (int q = 0; q < 4; q++) acc[h][mt][j][q] = 0.f;

        // ---- phase1: single K pass, A loaded once, both n-halves accumulated ----
        STAGE_B(0, 0);
        for (int kc = 0; kc < 4; kc++) {
            asm volatile("cp.async.wait_group 0;" ::: "memory");
            __syncthreads();
            if (kc < 3) STAGE_B(kc + 1, (kc + 1) & 1);
            uint32_t sB = sb + ((kc & 1) ? OB1 : OB0);
#pragma unroll
            for (int ks = 0; ks < 4; ks++) {
                int chA = (kc * 4 + ks) * 2 + chsel;
                uint32_t ah[2][4];
#pragma unroll
                for (int mt = 0; mt < 2; mt++) {
                    int row = wm * 32 + mt * 16 + rA;
                    uint32_t ad = sb + OZH + row * 512 + ((chA ^ (row & 7)) << 4);
                    LDMX4(ah[mt][0], ah[mt][1], ah[mt][2], ah[mt][3], ad);
                }
#pragma unroll
                for (int h = 0; h < 2; h++) {
#pragma unroll
                    for (int ng = 0; ng < 2; ng++) {
                        int row = h * 128 + wn * 32 + ng * 16 + rA;
                        uint32_t bd = sB + row * 128 + (((ks * 2 + chsel) ^ (row & 7)) << 4);
                        uint32_t b0, b1, b2, b3;
                        LDMX4(b0, b1, b2, b3, bd);
#pragma unroll
                        for (int mt = 0; mt < 2; mt++) {
                            mma16816(acc[h][mt][ng * 2 + 0], ah[mt], b0, b2);
                            mma16816(acc[h][mt][ng * 2 + 1], ah[mt], b1, b3);
                        }
                    }
                }
            }
        }

        // ---- per half: G -> fp16 smem, then phase2 accumulate into sfr ----
        for (int h = 0; h < 2; h++) {
            __syncthreads();
#pragma unroll
            for (int mt = 0; mt < 2; mt++)
#pragma unroll
                for (int j = 0; j < 4; j++) {
                    int c = wn * 32 + (j >> 1) * 16 + (j & 1) * 8 + (lane & 3) * 2;
#pragma unroll
                    for (int half = 0; half < 2; half++) {
                        int r = wm * 32 + mt * 16 + (lane >> 2) + half * 8;
                        float v0 = acc[h][mt][j][half * 2 + 0];
                        float v1 = acc[h][mt][j][half * 2 + 1];
                        uint32_t off = r * 256 + ((((c >> 3)) ^ (r & 7)) << 4) + (c & 7) * 2;
                        *(__half2*)(smem + OGH + off) = __half2(__float2half_rn(v0), __float2half_rn(v1));
                    }
                }
            __syncthreads();
            int slot = 0;
            for (int t = wid; t < NTILES; t += 16, slot++) {
                int rb, cb;
                if (T < 16) {
                    rb = cb = t * QB * T;
                } else {
                    int tbm = t / (MT * MT);
                    int rem = t % (MT * MT);
                    rb = tbm * T + (rem / MT) * 16;
                    cb = tbm * T + (rem % MT) * 16;
                }
#pragma unroll
                for (int kc = 0; kc < 8; kc++) {
                    int ch = kc * 2 + chsel;
                    int arow = rb + rA;
                    uint32_t aad = sb + OGH + arow * 256 + ((ch ^ (arow & 7)) << 4);
                    uint32_t gh[4];
                    LDMX4(gh[0], gh[1], gh[2], gh[3], aad);
                    int brow = cb + rA;
                    int chz = h * 16 + ch;
                    uint32_t bad = sb + OZH + brow * 512 + ((chz ^ (brow & 7)) << 4);
                    uint32_t zh2[4];
                    LDMX4(zh2[0], zh2[1], zh2[2], zh2[3], bad);
                    mma16816(sfr[slot][0], gh, zh2[0], zh2[2]);
                    mma16816(sfr[slot][1], gh, zh2[1], zh2[3]);
                }
            }
        }
        __syncthreads();

        // ---- S frags -> smem overlay ----
        float* sS = (float*)(smem + OSS);
        {
            int slot = 0;
            for (int t = wid; t < NTILES; t += 16, slot++) {
                int tbm = -1, ti = 0, tj = 0;
                if (T >= 16) {
                    tbm = t / (MT * MT);
                    int rem = t % (MT * MT);
                    ti = rem / MT;
                    tj = rem % MT;
                }
                int fr = lane >> 2, fc = (lane & 3) * 2;
#pragma unroll
                for (int j = 0; j < 2; j++)
#pragma unroll
                    for (int q = 0; q < 4; q++) {
                        int rr = fr + (q >> 1) * 8;
                        int cc = fc + (q & 1) + j * 8;
                        float v = sfr[slot][j][q];
                        if (T < 16) {
                            int qr = rr / T, qc = cc / T;
                            if (qr == qc && qr < QB) {
                                int bm = t * QB + qr;
                                if (bm < nbm) sS[(bm * T + rr - qr * T) * TCS + (cc - qc * T)] = v;
                            }
                        } else {
                            if (tbm < nbm && ti * 16 + rr < T && tj * 16 + cc < T)
                                sS[(tbm * T + ti * 16 + rr) * TCS + tj * 16 + cc] = v;
                        }
                    }
            }
        }
        __syncthreads();

        // ---- softmax rows -> g_S ----
        float cterm = g_cc[layer];
        const float* zu = (const float*)(smem + OZU) + layer * 128;
        const float* zv = (const float*)(smem + OZV) + layer * 128;
        int e = lane;
        for (int rho = wid; rho < nrows; rho += 16) {
            int bm = rho / T, l = rho % T;
            const float* row = sS + (bm * T + l) * TCS;
            bool v0 = (e < T);
            bool v1 = (T > 32) && (e + 32 < T);
            float zul = zu[rho];
            float x0 = v0 ? SCALE * (row[e] + zul + zv[bm * T + e] + cterm) : -1e30f;
            float x1 = v1 ? SCALE * (row[e + 32] + zul + zv[bm * T + e + 32] + cterm) : -1e30f;
            float mx = fmaxf(x0, x1);
#pragma unroll
            for (int o = 16; o; o >>= 1) mx = fmaxf(mx, __shfl_xor_sync(0xffffffffu, mx, o));
            float e0 = v0 ? __expf(x0 - mx) : 0.f;
            float e1 = v1 ? __expf(x1 - mx) : 0.f;
            float ssum = e0 + e1;
#pragma unroll
            for (int o = 16; o; o >>= 1) ssum += __shfl_xor_sync(0xffffffffu, ssum, o);
            float inv = 1.0f / ssum;
            float* So = g_S + ((size_t)layer * BM + bm0 + bm) * T * T + (size_t)l * T;
            if (v0) So[e] = e0 * inv;
            if (v1) So[e + 32] = e1 * inv;
        }
    }
#undef STAGE_B
}

// ---------------- channel mean + expand (fused) ----------------
template <int T, int P, bool TILE>
__global__ __launch_bounds__(256) void mean_expand_kernel(float* __restrict__ out) {
    constexpr int TT = T * T;
    __shared__ float sA[TT];
    int b = blockIdx.x, layer = blockIdx.y;
    const float* Sb = g_S + ((size_t)layer * BM + (size_t)b * MN) * TT;
    for (int r = threadIdx.x; r < TT; r += 256) {
        float s = 0.f;
#pragma unroll 5
        for (int m = 0; m < MN; m++) s += Sb[(size_t)m * TT + r];
        sA[r] = s * (1.0f / MN);
    }
    __syncthreads();
    float* ob = out + ((size_t)layer * BN + b) * LL;
    for (int i = threadIdx.x; i < LL; i += 256) {
        int l = i / LN, s = i - l * LN;
        int al = TILE ? (l % P) : (l / P);
        int as = TILE ? (s % P) : (s / P);
        ob[i] = sA[al * T + as];
    }
}

// ---------------- host orchestration ----------------
template <int T, int C, int P, bool TILE>
static void run_branch(int br, int peoff, float* outbase) {
    constexpr int QB = (T < 16) ? (16 / T) : 1;
    constexpr int NB = (T < 16) ? (8 * QB) : (128 / T);
    int nblk = (BM + NB - 1) / NB;
    cudaFuncSetAttribute(fused_kernel<T, C>, cudaFuncAttributeMaxDynamicSharedMemorySize, FUSED_SMEM);
    fused_kernel<T, C><<<nblk, 512, FUSED_SMEM>>>(br, peoff);
    mean_expand_kernel<T, P, TILE><<<dim3(BN, ELN), 256>>>(outbase);
}

extern "C" void kernel_launch(void* const* d_in, const int* in_sizes, int n_in,
                              void* d_out, int out_size) {
    const float* x = (const float*)d_in[0];
    const float* Wq = (const float*)d_in[7];
    const float* bq = (const float*)d_in[8];
    const float* Wk = (const float*)d_in[9];
    const float* bk = (const float*)d_in[10];
    float* out = (float*)d_out;

    k1_kernel<<<2614, 256>>>(x, Wq, Wk, bq, bk,
                             (const float*)d_in[1], (const float*)d_in[2],
                             (const float*)d_in[3], (const float*)d_in[4],
                             (const float*)d_in[5], (const float*)d_in[6]);
    meffT_kernel<<<dim3(256, ELN), 256>>>();

    run_branch<35, 3, 3, false>(0, 0, out + (size_t)0 * BN * LL);
    run_branch<3, 35, 3, true>(1, 35, out + (size_t)9 * BN * LL);
    run_branch<21, 5, 5, false>(2, 38, out + (size_t)3 * BN * LL);
    run_branch<5, 21, 5, true>(3, 59, out + (size_t)12 * BN * LL);
    run_branch<15, 7, 7, false>(4, 64, out + (size_t)6 * BN * LL);
    run_branch<7, 15, 7, true>(5, 79, out + (size_t)15 * BN * LL);
}

// round 15
// speedup vs baseline: 1.4138x; 1.0861x over previous
#include <cuda_runtime.h>
#include <cuda_fp16.h>
#include <math.h>
#include <cstdint>

#define BN 128
#define LN 105
#define MN 55
#define DN 256
#define ELN 3
static constexpr int BM = BN * MN;      // 7040
static constexpr int LL = LN * LN;      // 11025
static constexpr float SCALE = 0.0625f; // 1/sqrt(256)

// per-branch g_S offsets (floats): 3*BM*cum(T^2), order T=35,3,21,5,15,7
static constexpr size_t SOFF0 = 0;
static constexpr size_t SOFF1 = (size_t)3 * BM * 1225;
static constexpr size_t SOFF2 = (size_t)3 * BM * 1234;
static constexpr size_t SOFF3 = (size_t)3 * BM * 1675;
static constexpr size_t SOFF4 = (size_t)3 * BM * 1700;
static constexpr size_t SOFF5 = (size_t)3 * BM * 1925;
static constexpr size_t STOT  = (size_t)3 * BM * 1974;

// ---------------- scratch (device globals) ----------------
__device__ __align__(128) float g_xt[BM * LN];
__device__ __align__(128) float g_meff[ELN * DN * DN];
__device__ __align__(128) __half g_mth[ELN * DN * DN];    // MeffT [n][k] fp16
__device__ __align__(128) __half g_wth[6 * DN * DN];      // conv W fp16 padded
__device__ __align__(128) float g_pe[86 * DN];            // PE tables
__device__ float g_u[ELN * DN];
__device__ float g_v[ELN * DN];
__device__ float g_cc[ELN];
__device__ __align__(128) float g_S[STOT];

// ---------------- helpers ----------------
__device__ __forceinline__ uint32_t smem_u32(const void* p) {
    uint32_t a;
    asm("{ .reg .u64 t; cvta.to.shared.u64 t, %1; cvt.u32.u64 %0, t; }" : "=r"(a) : "l"(p));
    return a;
}
__device__ __forceinline__ void cp_async16(uint32_t saddr, const void* gptr) {
    asm volatile("cp.async.ca.shared.global [%0], [%1], 16;" :: "r"(saddr), "l"(gptr) : "memory");
}
__device__ __forceinline__ void mma16816(float* d, const uint32_t* a, uint32_t b0, uint32_t b1) {
    asm volatile(
        "mma.sync.aligned.m16n8k16.row.col.f32.f16.f16.f32 "
        "{%0,%1,%2,%3}, {%4,%5,%6,%7}, {%8,%9}, {%0,%1,%2,%3};"
        : "+f"(d[0]), "+f"(d[1]), "+f"(d[2]), "+f"(d[3])
        : "r"(a[0]), "r"(a[1]), "r"(a[2]), "r"(a[3]), "r"(b0), "r"(b1));
}
#define LDMX4(r0, r1, r2, r3, addr) \
    asm volatile("ldmatrix.sync.aligned.m8n8.x4.shared.b16 {%0,%1,%2,%3}, [%4];" \
        : "=r"(r0), "=r"(r1), "=r"(r2), "=r"(r3) : "r"(addr))

// ---------------- K1: revin + meff + uvc + wth + pe ----------------
__constant__ int c_wC[6] = {3, 35, 5, 21, 7, 15};
__constant__ int c_peS[7] = {0, 35, 38, 59, 64, 79, 86};

__global__ __launch_bounds__(256) void k1_kernel(
    const float* __restrict__ x,
    const float* __restrict__ Wq, const float* __restrict__ Wk,
    const float* __restrict__ bq, const float* __restrict__ bk,
    const float* __restrict__ w0, const float* __restrict__ w1,
    const float* __restrict__ w2, const float* __restrict__ w3,
    const float* __restrict__ w4, const float* __restrict__ w5) {
    int blk = blockIdx.x;
    int tid = threadIdx.x;
    if (blk < 128) {
        __shared__ float sx[LN * MN];
        __shared__ float smean[MN], sinv[MN];
        int b = blk;
        const float* xb = x + (size_t)b * LN * MN;
        for (int i = tid; i < LN * MN; i += 256) sx[i] = xb[i];
        __syncthreads();
        for (int m = tid; m < MN; m += 256) {
            float s = 0.f, s2 = 0.f;
            for (int l = 0; l < LN; l++) { float v = sx[l * MN + m]; s += v; s2 += v * v; }
            float mean = s * (1.0f / LN);
            float var = s2 * (1.0f / LN) - mean * mean;
            smean[m] = mean;
            sinv[m] = rsqrtf(var + 1e-5f);
        }
        __syncthreads();
        float* ob = g_xt + (size_t)b * MN * LN;
        for (int i = tid; i < MN * LN; i += 256) {
            int m = i / LN, l = i - m * LN;
            ob[i] = (sx[l * MN + m] - smean[m]) * sinv[m];
        }
    } else if (blk < 896) {
        __shared__ float sq[16][17], sk[16][17];
        int u = blk - 128;
        int l = u >> 8;
        int rem = u & 255;
        int i0 = (rem >> 4) * 16, j0 = (rem & 15) * 16;
        int ty = tid >> 4, tx = tid & 15;
        float acc = 0.f;
        const float* wq = Wq + (size_t)l * DN * DN;
        const float* wk = Wk + (size_t)l * DN * DN;
        for (int k0 = 0; k0 < DN; k0 += 16) {
            sq[ty][tx] = wq[(i0 + ty) * DN + k0 + tx];
            sk[ty][tx] = wk[(j0 + ty) * DN + k0 + tx];
            __syncthreads();
#pragma unroll
            for (int kk = 0; kk < 16; kk++) acc += sq[ty][kk] * sk[tx][kk];
            __syncthreads();
        }
        g_meff[(size_t)l * DN * DN + (i0 + ty) * DN + j0 + tx] = acc;
    } else if (blk < 992) {
        int u = blk - 896;
        int l = u >> 5, r = u & 31;
        int wid = tid >> 5, lane = tid & 31;
        int k = r * 8 + wid;
        float su = 0.f, sv = 0.f;
        const float* wq = Wq + (size_t)l * DN * DN + (size_t)k * DN;
        const float* wk = Wk + (size_t)l * DN * DN + (size_t)k * DN;
        for (int d = lane; d < DN; d += 32) {
            su += wq[d] * bk[l * DN + d];
            sv += wk[d] * bq[l * DN + d];
        }
#pragma unroll
        for (int o = 16; o; o >>= 1) {
            su += __shfl_xor_sync(0xffffffffu, su, o);
            sv += __shfl_xor_sync(0xffffffffu, sv, o);
        }
        if (lane == 0) {
            g_u[l * DN + k] = su;
            g_v[l * DN + k] = sv;
        }
        if (r == 0 && wid == 0) {
            float c = 0.f;
            for (int d = lane; d < DN; d += 32) c += bq[l * DN + d] * bk[l * DN + d];
#pragma unroll
            for (int o = 16; o; o >>= 1) c += __shfl_xor_sync(0xffffffffu, c, o);
            if (lane == 0) g_cc[l] = c;
        }
    } else if (blk < 2528) {
        int idx = (blk - 992) * 256 + tid;
        int br = idx >> 16;
        int rem = idx & 65535;
        int d = rem >> 8, k = rem & 255;
        int C3 = c_wC[br] * 3;
        const float* wp = br == 0 ? w0 : br == 1 ? w1 : br == 2 ? w2 : br == 3 ? w3 : br == 4 ? w4 : w5;
        float v = (k < C3) ? wp[d * C3 + k] : 0.f;
        g_wth[idx] = __float2half_rn(v);
    } else {
        int tg = blk - 2528;   // 0..85
        int d = tid;
        int seg = 0;
#pragma unroll
        for (int q = 1; q < 6; q++)
            if (tg >= c_peS[q]) seg = q;
        int t = tg - c_peS[seg];
        float freq = expf(-(float)(2 * (d >> 1)) * (9.210340371976184f / 256.f));
        float arg = (float)t * freq;
        g_pe[tg * DN + d] = (d & 1) ? cosf(arg) : sinf(arg);
    }
}

// ---------------- meffT: fp16 Meff^T ----------------
__global__ void meffT_kernel() {
    int l = blockIdx.y;
    int i = blockIdx.x * 256 + threadIdx.x;
    int n = i >> 8, k = i & 255;
    float v = g_meff[(size_t)l * DN * DN + k * DN + n];
    g_mth[(size_t)l * DN * DN + i] = __float2half_rn(v);
}

// ---------------- fused body (device, templated) ----------------
static constexpr int OZH = 0;        // Zh [128][256] fp16 (65536)
static constexpr int OGH = 65536;    // G / Xwin [128][128] fp16 (32768)
static constexpr int OB0 = 98304;    // B buf0 (32768)
static constexpr int OB1 = 131072;   // B buf1 (32768)
static constexpr int OSS = 98304;    // S overlay
static constexpr int OU  = 163840;
static constexpr int OV  = 166912;
static constexpr int OZU = 169984;
static constexpr int OZV = 171520;
static constexpr int FUSED_SMEM = 173056;

template <int T, int C>
__device__ __forceinline__ void fused_body(char* smem, int br, int peoff, int bm0, size_t soff) {
    constexpr int MT = (T + 15) / 16;
    constexpr int QB = (T < 16) ? (16 / T) : 1;
    constexpr int NB = (T < 16) ? (8 * QB) : (128 / T);
    constexpr int NTILES = (T < 16) ? 8 : (NB * MT * MT);
    constexpr int TC = (T + 3) & ~3;
    constexpr int TCS = TC + 1;
    constexpr int SLOTS = (NTILES + 15) / 16;
    constexpr int KST = (3 * C + 15) / 16;
    constexpr int NCH = (3 * C + 63) / 64;

    const uint32_t sb = smem_u32(smem);
    const int tid = threadIdx.x;
    const int lane = tid & 31;
    const int wid = tid >> 5;
    const int nbm = min(NB, BM - bm0);
    const int nrows = nbm * T;

    const int wm = wid >> 2, wn = wid & 3;
    const int rA = lane & 15;
    const int chsel = lane >> 4;

    for (int i = tid; i < 768; i += 512) {
        ((float*)(smem + OU))[i] = g_u[i];
        ((float*)(smem + OV))[i] = g_v[i];
    }

    // ---- build Xwin in OGH region ----
    for (int i = tid; i < 128 * 128; i += 512) {
        int r = i >> 7, k = i & 127;
        float v = 0.f;
        if (r < nrows && k < 3 * C) {
            int bmi = r / T, t = r - (r / T) * T;
            int c = k / 3, j = k - c * 3;
            int ts = t + j - 1;
            ts = (ts < 0) ? ts + T : (ts >= T ? ts - T : ts);
            v = __ldg(&g_xt[(size_t)(bm0 + bmi) * LN + ts * C + c]);
        }
        uint32_t off = r * 256 + (((k >> 3) ^ (r & 7)) << 4) + (k & 7) * 2;
        *(__half*)(smem + OGH + off) = __float2half_rn(v);
    }

    // ---- stage conv weights ----
    {
        const __half* Wsrc = g_wth + (size_t)br * DN * DN;
#pragma unroll
        for (int ch = 0; ch < NCH; ch++) {
            uint32_t dst = sb + (ch ? OB1 : OB0);
#pragma unroll
            for (int it = 0; it < 4; it++) {
                int idx = it * 512 + tid;
                int row = idx >> 3, col = idx & 7;
                uint32_t off = row * 128 + ((col ^ (row & 7)) << 4);
                cp_async16(dst + off, Wsrc + (size_t)row * DN + ch * 64 + col * 8);
            }
        }
        asm volatile("cp.async.commit_group;" ::: "memory");
    }
    asm volatile("cp.async.wait_group 0;" ::: "memory");
    __syncthreads();

    // ---- conv GEMM: Z = Xwin @ W^T (+PE) ----
    {
        float acc[2][2][4][4];
#pragma unroll
        for (int h = 0; h < 2; h++)
#pragma unroll
            for (int mt = 0; mt < 2; mt++)
#pragma unroll
                for (int j = 0; j < 4; j++)
#pragma unroll
                    for (int q = 0; q < 4; q++) acc[h][mt][j][q] = 0.f;

#pragma unroll
        for (int kstep = 0; kstep < KST; kstep++) {
            int buf = kstep >> 2, ksl = kstep & 3;
            uint32_t sB = sb + (buf ? OB1 : OB0);
            int chA = kstep * 2 + chsel;
            uint32_t ah[2][4];
#pragma unroll
            for (int mt = 0; mt < 2; mt++) {
                int row = wm * 32 + mt * 16 + rA;
                uint32_t ad = sb + OGH + row * 256 + ((chA ^ (row & 7)) << 4);
                LDMX4(ah[mt][0], ah[mt][1], ah[mt][2], ah[mt][3], ad);
            }
#pragma unroll
            for (int h = 0; h < 2; h++) {
#pragma unroll
                for (int ng = 0; ng < 2; ng++) {
                    int row = h * 128 + wn * 32 + ng * 16 + rA;
                    uint32_t bd = sB + row * 128 + (((ksl * 2 + chsel) ^ (row & 7)) << 4);
                    uint32_t b0, b1, b2, b3;
                    LDMX4(b0, b1, b2, b3, bd);
#pragma unroll
                    for (int mt = 0; mt < 2; mt++) {
                        mma16816(acc[h][mt][ng * 2 + 0], ah[mt], b0, b2);
                        mma16816(acc[h][mt][ng * 2 + 1], ah[mt], b1, b3);
                    }
                }
            }
        }
        const float* peb = g_pe + (size_t)peoff * DN;
#pragma unroll
        for (int h = 0; h < 2; h++)
#pragma unroll
            for (int mt = 0; mt < 2; mt++)
#pragma unroll
                for (int j = 0; j < 4; j++) {
                    int c = h * 128 + wn * 32 + (j >> 1) * 16 + (j & 1) * 8 + (lane & 3) * 2;
#pragma unroll
                    for (int half = 0; half < 2; half++) {
                        int r = wm * 32 + mt * 16 + (lane >> 2) + half * 8;
                        __half2 hv;
                        if (r < nrows) {
                            int t = r - (r / T) * T;
                            float2 pe = __ldg((const float2*)(peb + t * DN + c));
                            hv = __half2(__float2half_rn(acc[h][mt][j][half * 2 + 0] + pe.x),
                                         __float2half_rn(acc[h][mt][j][half * 2 + 1] + pe.y));
                        } else {
                            hv = __half2(__float2half_rn(0.f), __float2half_rn(0.f));
                        }
                        uint32_t off = r * 512 + ((((c >> 3)) ^ (r & 7)) << 4) + (c & 7) * 2;
                        *(__half2*)(smem + OZH + off) = hv;
                    }
                }
    }
    __syncthreads();

    // ---- zu/zv per row for ALL 3 layers ----
    {
        int r = tid >> 2, p = tid & 3;
        float au[3] = {0.f, 0.f, 0.f}, av[3] = {0.f, 0.f, 0.f};
        if (r < nrows) {
            const float4* su4 = (const float4*)(smem + OU);
            const float4* sv4 = (const float4*)(smem + OV);
            for (int c = p * 8; c < p * 8 + 8; c++) {
                uint32_t off = r * 512 + ((c ^ (r & 7)) << 4);
                uint4 zz = *(const uint4*)(smem + OZH + off);
                const __half2* hz = (const __half2*)&zz;
                float2 z0 = __half22float2(hz[0]);
                float2 z1 = __half22float2(hz[1]);
                float2 z2 = __half22float2(hz[2]);
                float2 z3 = __half22float2(hz[3]);
#pragma unroll
                for (int l = 0; l < 3; l++) {
                    int base = (l * DN + c * 8) >> 2;
                    float4 ua = su4[base], ub = su4[base + 1];
                    float4 va = sv4[base], vb = sv4[base + 1];
                    au[l] += z0.x * ua.x + z0.y * ua.y + z1.x * ua.z + z1.y * ua.w +
                             z2.x * ub.x + z2.y * ub.y + z3.x * ub.z + z3.y * ub.w;
                    av[l] += z0.x * va.x + z0.y * va.y + z1.x * va.z + z1.y * va.w +
                             z2.x * vb.x + z2.y * vb.y + z3.x * vb.z + z3.y * vb.w;
                }
            }
        }
#pragma unroll
        for (int l = 0; l < 3; l++) {
            au[l] += __shfl_xor_sync(0xffffffffu, au[l], 1);
            au[l] += __shfl_xor_sync(0xffffffffu, au[l], 2);
            av[l] += __shfl_xor_sync(0xffffffffu, av[l], 1);
            av[l] += __shfl_xor_sync(0xffffffffu, av[l], 2);
        }
        if (p == 0 && r < nrows) {
#pragma unroll
            for (int l = 0; l < 3; l++) {
                ((float*)(smem + OZU))[l * 128 + r] = au[l];
                ((float*)(smem + OZV))[l * 128 + r] = av[l];
            }
        }
    }

#define STAGE_B(kc, buf)                                                            \
    do {                                                                            \
        uint32_t dst_ = sb + ((buf) ? OB1 : OB0);                                   \
        _Pragma("unroll")                                                           \
        for (int it_ = 0; it_ < 4; it_++) {                                         \
            int idx_ = it_ * 512 + tid;                                             \
            int row_ = idx_ >> 3, col_ = idx_ & 7;                                  \
            uint32_t off_ = row_ * 128 + ((col_ ^ (row_ & 7)) << 4);                \
            cp_async16(dst_ + off_, Bh_src + (size_t)row_ * DN + (kc) * 64 + col_ * 8); \
        }                                                                           \
        asm volatile("cp.async.commit_group;" ::: "memory");                        \
    } while (0)

    for (int layer = 0; layer < ELN; layer++) {
        __syncthreads();

        float sfr[SLOTS][2][4];
#pragma unroll
        for (int s = 0; s < SLOTS; s++)
#pragma unroll
            for (int j = 0; j < 2; j++)
#pragma unroll
                for (int q = 0; q < 4; q++) sfr[s][j][q] = 0.f;

        const __half* Bh_src = g_mth + (size_t)layer * DN * DN;

        float acc[2][2][4][4];
#pragma unroll
        for (int h = 0; h < 2; h++)
#pragma unroll
            for (int mt = 0; mt < 2; mt++)
#pragma unroll
                for (int j = 0; j < 4; j++)
#pragma unroll
                    for (int q = 0; q < 4; q++) acc[h][mt][j][q] = 0.f;

        STAGE_B(0, 0);
        for (int kc = 0; kc < 4; kc++) {
            asm volatile("cp.async.wait_group 0;" ::: "memory");
            __syncthreads();
            if (kc < 3) STAGE_B(kc + 1, (kc + 1) & 1);
            uint32_t sB = sb + ((kc & 1) ? OB1 : OB0);
#pragma unroll
            for (int ks = 0; ks < 4; ks++) {
                int chA = (kc * 4 + ks) * 2 + chsel;
                uint32_t ah[2][4];
#pragma unroll
                for (int mt = 0; mt < 2; mt++) {
                    int row = wm * 32 + mt * 16 + rA;
                    uint32_t ad = sb + OZH + row * 512 + ((chA ^ (row & 7)) << 4);
                    LDMX4(ah[mt][0], ah[mt][1], ah[mt][2], ah[mt][3], ad);
                }
#pragma unroll
                for (int h = 0; h < 2; h++) {
#pragma unroll
                    for (int ng = 0; ng < 2; ng++) {
                        int row = h * 128 + wn * 32 + ng * 16 + rA;
                        uint32_t bd = sB + row * 128 + (((ks * 2 + chsel) ^ (row & 7)) << 4);
                        uint32_t b0, b1, b2, b3;
                        LDMX4(b0, b1, b2, b3, bd);
#pragma unroll
                        for (int mt = 0; mt < 2; mt++) {
                            mma16816(acc[h][mt][ng * 2 + 0], ah[mt], b0, b2);
                            mma16816(acc[h][mt][ng * 2 + 1], ah[mt], b1, b3);
                        }
                    }
                }
            }
        }

        for (int h = 0; h < 2; h++) {
            __syncthreads();
#pragma unroll
            for (int mt = 0; mt < 2; mt++)
#pragma unroll
                for (int j = 0; j < 4; j++) {
                    int c = wn * 32 + (j >> 1) * 16 + (j & 1) * 8 + (lane & 3) * 2;
#pragma unroll
                    for (int half = 0; half < 2; half++) {
                        int r = wm * 32 + mt * 16 + (lane >> 2) + half * 8;
                        float v0 = acc[h][mt][j][half * 2 + 0];
                        float v1 = acc[h][mt][j][half * 2 + 1];
                        uint32_t off = r * 256 + ((((c >> 3)) ^ (r & 7)) << 4) + (c & 7) * 2;
                        *(__half2*)(smem + OGH + off) = __half2(__float2half_rn(v0), __float2half_rn(v1));
                    }
                }
            __syncthreads();
            int slot = 0;
            for (int t = wid; t < NTILES; t += 16, slot++) {
                int rb, cb;
                if (T < 16) {
                    rb = cb = t * QB * T;
                } else {
                    int tbm = t / (MT * MT);
                    int rem = t % (MT * MT);
                    rb = tbm * T + (rem / MT) * 16;
                    cb = tbm * T + (rem % MT) * 16;
                }
#pragma unroll
                for (int kc = 0; kc < 8; kc++) {
                    int ch = kc * 2 + chsel;
                    int arow = rb + rA;
                    uint32_t aad = sb + OGH + arow * 256 + ((ch ^ (arow & 7)) << 4);
                    uint32_t gh[4];
                    LDMX4(gh[0], gh[1], gh[2], gh[3], aad);
                    int brow = cb + rA;
                    int chz = h * 16 + ch;
                    uint32_t bad = sb + OZH + brow * 512 + ((chz ^ (brow & 7)) << 4);
                    uint32_t zh2[4];
                    LDMX4(zh2[0], zh2[1], zh2[2], zh2[3], bad);
                    mma16816(sfr[slot][0], gh, zh2[0], zh2[2]);
                    mma16816(sfr[slot][1], gh, zh2[1], zh2[3]);
                }
            }
        }
        __syncthreads();

        float* sS = (float*)(smem + OSS);
        {
            int slot = 0;
            for (int t = wid; t < NTILES; t += 16, slot++) {
                int tbm = -1, ti = 0, tj = 0;
                if (T >= 16) {
                    tbm = t / (MT * MT);
                    int rem = t % (MT * MT);
                    ti = rem / MT;
                    tj = rem % MT;
                }
                int fr = lane >> 2, fc = (lane & 3) * 2;
#pragma unroll
                for (int j = 0; j < 2; j++)
#pragma unroll
                    for (int q = 0; q < 4; q++) {
                        int rr = fr + (q >> 1) * 8;
                        int cc = fc + (q & 1) + j * 8;
                        float v = sfr[slot][j][q];
                        if (T < 16) {
                            int qr = rr / T, qc = cc / T;
                            if (qr == qc && qr < QB) {
                                int bm = t * QB + qr;
                                if (bm < nbm) sS[(bm * T + rr - qr * T) * TCS + (cc - qc * T)] = v;
                            }
                        } else {
                            if (tbm < nbm && ti * 16 + rr < T && tj * 16 + cc < T)
                                sS[(tbm * T + ti * 16 + rr) * TCS + tj * 16 + cc] = v;
                        }
                    }
            }
        }
        __syncthreads();

        float cterm = g_cc[layer];
        const float* zu = (const float*)(smem + OZU) + layer * 128;
        const float* zv = (const float*)(smem + OZV) + layer * 128;
        int e = lane;
        for (int rho = wid; rho < nrows; rho += 16) {
            int bm = rho / T, l = rho % T;
            const float* row = sS + (bm * T + l) * TCS;
            bool v0 = (e < T);
            bool v1 = (T > 32) && (e + 32 < T);
            float zul = zu[rho];
            float x0 = v0 ? SCALE * (row[e] + zul + zv[bm * T + e] + cterm) : -1e30f;
            float x1 = v1 ? SCALE * (row[e + 32] + zul + zv[bm * T + e + 32] + cterm) : -1e30f;
            float mx = fmaxf(x0, x1);
#pragma unroll
            for (int o = 16; o; o >>= 1) mx = fmaxf(mx, __shfl_xor_sync(0xffffffffu, mx, o));
            float e0 = v0 ? __expf(x0 - mx) : 0.f;
            float e1 = v1 ? __expf(x1 - mx) : 0.f;
            float ssum = e0 + e1;
#pragma unroll
            for (int o = 16; o; o >>= 1) ssum += __shfl_xor_sync(0xffffffffu, ssum, o);
            float inv = 1.0f / ssum;
            float* So = g_S + soff + ((size_t)layer * BM + bm0 + bm) * T * T + (size_t)l * T;
            if (v0) So[e] = e0 * inv;
            if (v1) So[e + 32] = e1 * inv;
        }
    }
#undef STAGE_B
}

// ---------------- mega fused kernel: all 6 branches in one grid ----------------
__global__ __launch_bounds__(512, 1) void mega_fused_kernel() {
    extern __shared__ __align__(128) char smem[];
    int blk = blockIdx.x;
    if (blk < 2347) {
        fused_body<35, 3>(smem, 0, 0, blk * 3, SOFF0);
    } else if (blk < 2523) {
        fused_body<3, 35>(smem, 1, 35, (blk - 2347) * 40, SOFF1);
    } else if (blk < 3697) {
        fused_body<21, 5>(smem, 2, 38, (blk - 2523) * 6, SOFF2);
    } else if (blk < 3991) {
        fused_body<5, 21>(smem, 3, 59, (blk - 3697) * 24, SOFF3);
    } else if (blk < 4871) {
        fused_body<15, 7>(smem, 4, 64, (blk - 3991) * 8, SOFF4);
    } else {
        fused_body<7, 15>(smem, 5, 79, (blk - 4871) * 16, SOFF5);
    }
}

// ---------------- channel mean + expand (one mega launch) ----------------
template <int T, int P, bool TILE>
__device__ __forceinline__ void mean_expand_body(float* __restrict__ out, int b, int layer, size_t soff) {
    constexpr int TT = T * T;
    __shared__ float sA[35 * 35];
    const float* Sb = g_S + soff + ((size_t)layer * BM + (size_t)b * MN) * TT;
    for (int r = threadIdx.x; r < TT; r += 256) {
        float s = 0.f;
#pragma unroll 5
        for (int m = 0; m < MN; m++) s += Sb[(size_t)m * TT + r];
        sA[r] = s * (1.0f / MN);
    }
    __syncthreads();
    float* ob = out + ((size_t)layer * BN + b) * LL;
    for (int i = threadIdx.x; i < LL; i += 256) {
        int l = i / LN, s = i - l * LN;
        int al = TILE ? (l % P) : (l / P);
        int as = TILE ? (s % P) : (s / P);
        ob[i] = sA[al * T + as];
    }
}

__global__ __launch_bounds__(256) void mega_mean_kernel(float* __restrict__ out) {
    int blk = blockIdx.x;
    int seg = blk / 384;
    int rem = blk % 384;
    int b = rem & 127, layer = rem >> 7;
    switch (seg) {
        case 0: mean_expand_body<35, 3, false>(out + (size_t)0 * BN * LL, b, layer, SOFF0); break;
        case 1: mean_expand_body<3, 3, true>(out + (size_t)9 * BN * LL, b, layer, SOFF1); break;
        case 2: mean_expand_body<21, 5, false>(out + (size_t)3 * BN * LL, b, layer, SOFF2); break;
        case 3: mean_expand_body<5, 5, true>(out + (size_t)12 * BN * LL, b, layer, SOFF3); break;
        case 4: mean_expand_body<15, 7, false>(out + (size_t)6 * BN * LL, b, layer, SOFF4); break;
        default: mean_expand_body<7, 7, true>(out + (size_t)15 * BN * LL, b, layer, SOFF5); break;
    }
}

extern "C" void kernel_launch(void* const* d_in, const int* in_sizes, int n_in,
                              void* d_out, int out_size) {
    const float* x = (const float*)d_in[0];
    const float* Wq = (const float*)d_in[7];
    const float* bq = (const float*)d_in[8];
    const float* Wk = (const float*)d_in[9];
    const float* bk = (const float*)d_in[10];
    float* out = (float*)d_out;

    cudaFuncSetAttribute(mega_fused_kernel, cudaFuncAttributeMaxDynamicSharedMemorySize, FUSED_SMEM);

    k1_kernel<<<2614, 256>>>(x, Wq, Wk, bq, bk,
                             (const float*)d_in[1], (const float*)d_in[2],
                             (const float*)d_in[3], (const float*)d_in[4],
                             (const float*)d_in[5], (const float*)d_in[6]);
    meffT_kernel<<<dim3(256, ELN), 256>>>();
    mega_fused_kernel<<<5311, 512, FUSED_SMEM>>>();
    mega_mean_kernel<<<2304, 256>>>(out);
}

// round 16
// speedup vs baseline: 1.4303x; 1.0117x over previous
#include <cuda_runtime.h>
#include <cuda_fp16.h>
#include <math.h>
#include <cstdint>

#define BN 128
#define LN 105
#define MN 55
#define DN 256
#define ELN 3
static constexpr int BM = BN * MN;      // 7040
static constexpr int LL = LN * LN;      // 11025
static constexpr float SCALE = 0.0625f; // 1/sqrt(256)

// per-branch g_S offsets (halves): 3*BM*cum(T^2), order T=35,3,21,5,15,7
static constexpr size_t SOFF0 = 0;
static constexpr size_t SOFF1 = (size_t)3 * BM * 1225;
static constexpr size_t SOFF2 = (size_t)3 * BM * 1234;
static constexpr size_t SOFF3 = (size_t)3 * BM * 1675;
static constexpr size_t SOFF4 = (size_t)3 * BM * 1700;
static constexpr size_t SOFF5 = (size_t)3 * BM * 1925;
static constexpr size_t STOT  = (size_t)3 * BM * 1974;

// ---------------- scratch (device globals) ----------------
__device__ __align__(128) float g_xt[BM * LN];
__device__ __align__(128) __half g_mth[ELN * DN * DN];    // MeffT [n][k] fp16
__device__ __align__(128) __half g_wth[6 * DN * DN];      // conv W fp16 padded
__device__ __align__(128) float g_pe[86 * DN];            // PE tables
__device__ float g_u[ELN * DN];
__device__ float g_v[ELN * DN];
__device__ float g_cc[ELN];
__device__ __align__(128) __half g_S[STOT];

// ---------------- helpers ----------------
__device__ __forceinline__ uint32_t smem_u32(const void* p) {
    uint32_t a;
    asm("{ .reg .u64 t; cvta.to.shared.u64 t, %1; cvt.u32.u64 %0, t; }" : "=r"(a) : "l"(p));
    return a;
}
__device__ __forceinline__ void cp_async16(uint32_t saddr, const void* gptr) {
    asm volatile("cp.async.ca.shared.global [%0], [%1], 16;" :: "r"(saddr), "l"(gptr) : "memory");
}
__device__ __forceinline__ void mma16816(float* d, const uint32_t* a, uint32_t b0, uint32_t b1) {
    asm volatile(
        "mma.sync.aligned.m16n8k16.row.col.f32.f16.f16.f32 "
        "{%0,%1,%2,%3}, {%4,%5,%6,%7}, {%8,%9}, {%0,%1,%2,%3};"
        : "+f"(d[0]), "+f"(d[1]), "+f"(d[2]), "+f"(d[3])
        : "r"(a[0]), "r"(a[1]), "r"(a[2]), "r"(a[3]), "r"(b0), "r"(b1));
}
#define LDMX4(r0, r1, r2, r3, addr) \
    asm volatile("ldmatrix.sync.aligned.m8n8.x4.shared.b16 {%0,%1,%2,%3}, [%4];" \
        : "=r"(r0), "=r"(r1), "=r"(r2), "=r"(r3) : "r"(addr))

// ---------------- K1: revin + meffT(fp16 direct) + uvc + wth + pe ----------------
__constant__ int c_wC[6] = {3, 35, 5, 21, 7, 15};
__constant__ int c_peS[7] = {0, 35, 38, 59, 64, 79, 86};

__global__ __launch_bounds__(256) void k1_kernel(
    const float* __restrict__ x,
    const float* __restrict__ Wq, const float* __restrict__ Wk,
    const float* __restrict__ bq, const float* __restrict__ bk,
    const float* __restrict__ w0, const float* __restrict__ w1,
    const float* __restrict__ w2, const float* __restrict__ w3,
    const float* __restrict__ w4, const float* __restrict__ w5) {
    int blk = blockIdx.x;
    int tid = threadIdx.x;
    if (blk < 128) {
        __shared__ float sx[LN * MN];
        __shared__ float smean[MN], sinv[MN];
        int b = blk;
        const float* xb = x + (size_t)b * LN * MN;
        for (int i = tid; i < LN * MN; i += 256) sx[i] = xb[i];
        __syncthreads();
        for (int m = tid; m < MN; m += 256) {
            float s = 0.f, s2 = 0.f;
            for (int l = 0; l < LN; l++) { float v = sx[l * MN + m]; s += v; s2 += v * v; }
            float mean = s * (1.0f / LN);
            float var = s2 * (1.0f / LN) - mean * mean;
            smean[m] = mean;
            sinv[m] = rsqrtf(var + 1e-5f);
        }
        __syncthreads();
        float* ob = g_xt + (size_t)b * MN * LN;
        for (int i = tid; i < MN * LN; i += 256) {
            int m = i / LN, l = i - m * LN;
            ob[i] = (sx[l * MN + m] - smean[m]) * sinv[m];
        }
    } else if (blk < 896) {
        // meff^T fp16 direct: mth[l][n][k] = fp16(Wq_row(k) . Wk_row(n))
        __shared__ float sq[16][17], sk[16][17];
        int u = blk - 128;
        int l = u >> 8;
        int rem = u & 255;
        int i0 = (rem >> 4) * 16, j0 = (rem & 15) * 16;   // i = k index (Wq rows), j = n index (Wk rows)
        int ty = tid >> 4, tx = tid & 15;
        float acc = 0.f;
        const float* wq = Wq + (size_t)l * DN * DN;
        const float* wk = Wk + (size_t)l * DN * DN;
        for (int k0 = 0; k0 < DN; k0 += 16) {
            sq[ty][tx] = wq[(i0 + ty) * DN + k0 + tx];
            sk[ty][tx] = wk[(j0 + ty) * DN + k0 + tx];
            __syncthreads();
#pragma unroll
            for (int kk = 0; kk < 16; kk++) acc += sq[tx][kk] * sk[ty][kk];
            __syncthreads();
        }
        // thread (ty,tx): n = j0+ty, k = i0+tx  -> coalesced in tx
        g_mth[(size_t)l * DN * DN + (size_t)(j0 + ty) * DN + (i0 + tx)] = __float2half_rn(acc);
    } else if (blk < 992) {
        int u = blk - 896;
        int l = u >> 5, r = u & 31;
        int wid = tid >> 5, lane = tid & 31;
        int k = r * 8 + wid;
        float su = 0.f, sv = 0.f;
        const float* wq = Wq + (size_t)l * DN * DN + (size_t)k * DN;
        const float* wk = Wk + (size_t)l * DN * DN + (size_t)k * DN;
        for (int d = lane; d < DN; d += 32) {
            su += wq[d] * bk[l * DN + d];
            sv += wk[d] * bq[l * DN + d];
        }
#pragma unroll
        for (int o = 16; o; o >>= 1) {
            su += __shfl_xor_sync(0xffffffffu, su, o);
            sv += __shfl_xor_sync(0xffffffffu, sv, o);
        }
        if (lane == 0) {
            g_u[l * DN + k] = su;
            g_v[l * DN + k] = sv;
        }
        if (r == 0 && wid == 0) {
            float c = 0.f;
            for (int d = lane; d < DN; d += 32) c += bq[l * DN + d] * bk[l * DN + d];
#pragma unroll
            for (int o = 16; o; o >>= 1) c += __shfl_xor_sync(0xffffffffu, c, o);
            if (lane == 0) g_cc[l] = c;
        }
    } else if (blk < 2528) {
        int idx = (blk - 992) * 256 + tid;
        int br = idx >> 16;
        int rem = idx & 65535;
        int d = rem >> 8, k = rem & 255;
        int C3 = c_wC[br] * 3;
        const float* wp = br == 0 ? w0 : br == 1 ? w1 : br == 2 ? w2 : br == 3 ? w3 : br == 4 ? w4 : w5;
        float v = (k < C3) ? wp[d * C3 + k] : 0.f;
        g_wth[idx] = __float2half_rn(v);
    } else {
        int tg = blk - 2528;   // 0..85
        int d = tid;
        int seg = 0;
#pragma unroll
        for (int q = 1; q < 6; q++)
            if (tg >= c_peS[q]) seg = q;
        int t = tg - c_peS[seg];
        float freq = expf(-(float)(2 * (d >> 1)) * (9.210340371976184f / 256.f));
        float arg = (float)t * freq;
        g_pe[tg * DN + d] = (d & 1) ? cosf(arg) : sinf(arg);
    }
}

// ---------------- fused body (device, templated) ----------------
static constexpr int OZH = 0;        // Zh [128][256] fp16 (65536)
static constexpr int OGH = 65536;    // G / Xwin [128][128] fp16 (32768)
static constexpr int OB0 = 98304;    // B buf0 (32768)
static constexpr int OB1 = 131072;   // B buf1 (32768)
static constexpr int OSS = 98304;    // S overlay
static constexpr int OU  = 163840;
static constexpr int OV  = 166912;
static constexpr int OZU = 169984;
static constexpr int OZV = 171520;
static constexpr int FUSED_SMEM = 173056;

template <int T, int C>
__device__ __forceinline__ void fused_body(char* smem, int br, int peoff, int bm0, size_t soff) {
    constexpr int MT = (T + 15) / 16;
    constexpr int QB = (T < 16) ? (16 / T) : 1;
    constexpr int NB = (T < 16) ? (8 * QB) : (128 / T);
    constexpr int NTILES = (T < 16) ? 8 : (NB * MT * MT);
    constexpr int TC = (T + 3) & ~3;
    constexpr int TCS = TC + 1;
    constexpr int SLOTS = (NTILES + 15) / 16;
    constexpr int KST = (3 * C + 15) / 16;
    constexpr int NCH = (3 * C + 63) / 64;

    const uint32_t sb = smem_u32(smem);
    const int tid = threadIdx.x;
    const int lane = tid & 31;
    const int wid = tid >> 5;
    const int nbm = min(NB, BM - bm0);
    const int nrows = nbm * T;

    const int wm = wid >> 2, wn = wid & 3;
    const int rA = lane & 15;
    const int chsel = lane >> 4;

    for (int i = tid; i < 768; i += 512) {
        ((float*)(smem + OU))[i] = g_u[i];
        ((float*)(smem + OV))[i] = g_v[i];
    }

    // ---- build Xwin in OGH region ----
    for (int i = tid; i < 128 * 128; i += 512) {
        int r = i >> 7, k = i & 127;
        float v = 0.f;
        if (r < nrows && k < 3 * C) {
            int bmi = r / T, t = r - (r / T) * T;
            int c = k / 3, j = k - c * 3;
            int ts = t + j - 1;
            ts = (ts < 0) ? ts + T : (ts >= T ? ts - T : ts);
            v = __ldg(&g_xt[(size_t)(bm0 + bmi) * LN + ts * C + c]);
        }
        uint32_t off = r * 256 + (((k >> 3) ^ (r & 7)) << 4) + (k & 7) * 2;
        *(__half*)(smem + OGH + off) = __float2half_rn(v);
    }

    // ---- stage conv weights ----
    {
        const __half* Wsrc = g_wth + (size_t)br * DN * DN;
#pragma unroll
        for (int ch = 0; ch < NCH; ch++) {
            uint32_t dst = sb + (ch ? OB1 : OB0);
#pragma unroll
            for (int it = 0; it < 4; it++) {
                int idx = it * 512 + tid;
                int row = idx >> 3, col = idx & 7;
                uint32_t off = row * 128 + ((col ^ (row & 7)) << 4);
                cp_async16(dst + off, Wsrc + (size_t)row * DN + ch * 64 + col * 8);
            }
        }
        asm volatile("cp.async.commit_group;" ::: "memory");
    }
    asm volatile("cp.async.wait_group 0;" ::: "memory");
    __syncthreads();

    // ---- conv GEMM: Z = Xwin @ W^T (+PE) ----
    {
        float acc[2][2][4][4];
#pragma unroll
        for (int h = 0; h < 2; h++)
#pragma unroll
            for (int mt = 0; mt < 2; mt++)
#pragma unroll
                for (int j = 0; j < 4; j++)
#pragma unroll
                    for (int q = 0; q < 4; q++) acc[h][mt][j][q] = 0.f;

#pragma unroll
        for (int kstep = 0; kstep < KST; kstep++) {
            int buf = kstep >> 2, ksl = kstep & 3;
            uint32_t sB = sb + (buf ? OB1 : OB0);
            int chA = kstep * 2 + chsel;
            uint32_t ah[2][4];
#pragma unroll
            for (int mt = 0; mt < 2; mt++) {
                int row = wm * 32 + mt * 16 + rA;
                uint32_t ad = sb + OGH + row * 256 + ((chA ^ (row & 7)) << 4);
                LDMX4(ah[mt][0], ah[mt][1], ah[mt][2], ah[mt][3], ad);
            }
#pragma unroll
            for (int h = 0; h < 2; h++) {
#pragma unroll
                for (int ng = 0; ng < 2; ng++) {
                    int row = h * 128 + wn * 32 + ng * 16 + rA;
                    uint32_t bd = sB + row * 128 + (((ksl * 2 + chsel) ^ (row & 7)) << 4);
                    uint32_t b0, b1, b2, b3;
                    LDMX4(b0, b1, b2, b3, bd);
#pragma unroll
                    for (int mt = 0; mt < 2; mt++) {
                        mma16816(acc[h][mt][ng * 2 + 0], ah[mt], b0, b2);
                        mma16816(acc[h][mt][ng * 2 + 1], ah[mt], b1, b3);
                    }
                }
            }
        }
        const float* peb = g_pe + (size_t)peoff * DN;
#pragma unroll
        for (int h = 0; h < 2; h++)
#pragma unroll
            for (int mt = 0; mt < 2; mt++)
#pragma unroll
                for (int j = 0; j < 4; j++) {
                    int c = h * 128 + wn * 32 + (j >> 1) * 16 + (j & 1) * 8 + (lane & 3) * 2;
#pragma unroll
                    for (int half = 0; half < 2; half++) {
                        int r = wm * 32 + mt * 16 + (lane >> 2) + half * 8;
                        __half2 hv;
                        if (r < nrows) {
                            int t = r - (r / T) * T;
                            float2 pe = __ldg((const float2*)(peb + t * DN + c));
                            hv = __half2(__float2half_rn(acc[h][mt][j][half * 2 + 0] + pe.x),
                                         __float2half_rn(acc[h][mt][j][half * 2 + 1] + pe.y));
                        } else {
                            hv = __half2(__float2half_rn(0.f), __float2half_rn(0.f));
                        }
                        uint32_t off = r * 512 + ((((c >> 3)) ^ (r & 7)) << 4) + (c & 7) * 2;
                        *(__half2*)(smem + OZH + off) = hv;
                    }
                }
    }
    __syncthreads();

    // ---- zu/zv per row for ALL 3 layers ----
    {
        int r = tid >> 2, p = tid & 3;
        float au[3] = {0.f, 0.f, 0.f}, av[3] = {0.f, 0.f, 0.f};
        if (r < nrows) {
            const float4* su4 = (const float4*)(smem + OU);
            const float4* sv4 = (const float4*)(smem + OV);
            for (int c = p * 8; c < p * 8 + 8; c++) {
                uint32_t off = r * 512 + ((c ^ (r & 7)) << 4);
                uint4 zz = *(const uint4*)(smem + OZH + off);
                const __half2* hz = (const __half2*)&zz;
                float2 z0 = __half22float2(hz[0]);
                float2 z1 = __half22float2(hz[1]);
                float2 z2 = __half22float2(hz[2]);
                float2 z3 = __half22float2(hz[3]);
#pragma unroll
                for (int l = 0; l < 3; l++) {
                    int base = (l * DN + c * 8) >> 2;
                    float4 ua = su4[base], ub = su4[base + 1];
                    float4 va = sv4[base], vb = sv4[base + 1];
                    au[l] += z0.x * ua.x + z0.y * ua.y + z1.x * ua.z + z1.y * ua.w +
                             z2.x * ub.x + z2.y * ub.y + z3.x * ub.z + z3.y * ub.w;
                    av[l] += z0.x * va.x + z0.y * va.y + z1.x * va.z + z1.y * va.w +
                             z2.x * vb.x + z2.y * vb.y + z3.x * vb.z + z3.y * vb.w;
                }
            }
        }
#pragma unroll
        for (int l = 0; l < 3; l++) {
            au[l] += __shfl_xor_sync(0xffffffffu, au[l], 1);
            au[l] += __shfl_xor_sync(0xffffffffu, au[l], 2);
            av[l] += __shfl_xor_sync(0xffffffffu, av[l], 1);
            av[l] += __shfl_xor_sync(0xffffffffu, av[l], 2);
        }
        if (p == 0 && r < nrows) {
#pragma unroll
            for (int l = 0; l < 3; l++) {
                ((float*)(smem + OZU))[l * 128 + r] = au[l];
                ((float*)(smem + OZV))[l * 128 + r] = av[l];
            }
        }
    }

#define STAGE_B(kc, buf)                                                            \
    do {                                                                            \
        uint32_t dst_ = sb + ((buf) ? OB1 : OB0);                                   \
        _Pragma("unroll")                                                           \
        for (int it_ = 0; it_ < 4; it_++) {                                         \
            int idx_ = it_ * 512 + tid;                                             \
            int row_ = idx_ >> 3, col_ = idx_ & 7;                                  \
            uint32_t off_ = row_ * 128 + ((col_ ^ (row_ & 7)) << 4);                \
            cp_async16(dst_ + off_, Bh_src + (size_t)row_ * DN + (kc) * 64 + col_ * 8); \
        }                                                                           \
        asm volatile("cp.async.commit_group;" ::: "memory");                        \
    } while (0)

    for (int layer = 0; layer < ELN; layer++) {
        __syncthreads();

        float sfr[SLOTS][2][4];
#pragma unroll
        for (int s = 0; s < SLOTS; s++)
#pragma unroll
            for (int j = 0; j < 2; j++)
#pragma unroll
                for (int q = 0; q < 4; q++) sfr[s][j][q] = 0.f;

        const __half* Bh_src = g_mth + (size_t)layer * DN * DN;

        float acc[2][2][4][4];
#pragma unroll
        for (int h = 0; h < 2; h++)
#pragma unroll
            for (int mt = 0; mt < 2; mt++)
#pragma unroll
                for (int j = 0; j < 4; j++)
#pragma unroll
                    for (int q = 0; q < 4; q++) acc[h][mt][j][q] = 0.f;

        STAGE_B(0, 0);
        for (int kc = 0; kc < 4; kc++) {
            asm volatile("cp.async.wait_group 0;" ::: "memory");
            __syncthreads();
            if (kc < 3) STAGE_B(kc + 1, (kc + 1) & 1);
            uint32_t sB = sb + ((kc & 1) ? OB1 : OB0);
#pragma unroll
            for (int ks = 0; ks < 4; ks++) {
                int chA = (kc * 4 + ks) * 2 + chsel;
                uint32_t ah[2][4];
#pragma unroll
                for (int mt = 0; mt < 2; mt++) {
                    int row = wm * 32 + mt * 16 + rA;
                    uint32_t ad = sb + OZH + row * 512 + ((chA ^ (row & 7)) << 4);
                    LDMX4(ah[mt][0], ah[mt][1], ah[mt][2], ah[mt][3], ad);
                }
#pragma unroll
                for (int h = 0; h < 2; h++) {
#pragma unroll
                    for (int ng = 0; ng < 2; ng++) {
                        int row = h * 128 + wn * 32 + ng * 16 + rA;
                        uint32_t bd = sB + row * 128 + (((ks * 2 + chsel) ^ (row & 7)) << 4);
                        uint32_t b0, b1, b2, b3;
                        LDMX4(b0, b1, b2, b3, bd);
#pragma unroll
                        for (int mt = 0; mt < 2; mt++) {
                            mma16816(acc[h][mt][ng * 2 + 0], ah[mt], b0, b2);
                            mma16816(acc[h][mt][ng * 2 + 1], ah[mt], b1, b3);
                        }
                    }
                }
            }
        }

        for (int h = 0; h < 2; h++) {
            __syncthreads();
#pragma unroll
            for (int mt = 0; mt < 2; mt++)
#pragma unroll
                for (int j = 0; j < 4; j++) {
                    int c = wn * 32 + (j >> 1) * 16 + (j & 1) * 8 + (lane & 3) * 2;
#pragma unroll
                    for (int half = 0; half < 2; half++) {
                        int r = wm * 32 + mt * 16 + (lane >> 2) + half * 8;
                        float v0 = acc[h][mt][j][half * 2 + 0];
                        float v1 = acc[h][mt][j][half * 2 + 1];
                        uint32_t off = r * 256 + ((((c >> 3)) ^ (r & 7)) << 4) + (c & 7) * 2;
                        *(__half2*)(smem + OGH + off) = __half2(__float2half_rn(v0), __float2half_rn(v1));
                    }
                }
            __syncthreads();
            int slot = 0;
            for (int t = wid; t < NTILES; t += 16, slot++) {
                int rb, cb;
                if (T < 16) {
                    rb = cb = t * QB * T;
                } else {
                    int tbm = t / (MT * MT);
                    int rem = t % (MT * MT);
                    rb = tbm * T + (rem / MT) * 16;
                    cb = tbm * T + (rem % MT) * 16;
                }
#pragma unroll
                for (int kc = 0; kc < 8; kc++) {
                    int ch = kc * 2 + chsel;
                    int arow = rb + rA;
                    uint32_t aad = sb + OGH + arow * 256 + ((ch ^ (arow & 7)) << 4);
                    uint32_t gh[4];
                    LDMX4(gh[0], gh[1], gh[2], gh[3], aad);
                    int brow = cb + rA;
                    int chz = h * 16 + ch;
                    uint32_t bad = sb + OZH + brow * 512 + ((chz ^ (brow & 7)) << 4);
                    uint32_t zh2[4];
                    LDMX4(zh2[0], zh2[1], zh2[2], zh2[3], bad);
                    mma16816(sfr[slot][0], gh, zh2[0], zh2[2]);
                    mma16816(sfr[slot][1], gh, zh2[1], zh2[3]);
                }
            }
        }
        __syncthreads();

        float* sS = (float*)(smem + OSS);
        {
            int slot = 0;
            for (int t = wid; t < NTILES; t += 16, slot++) {
                int tbm = -1, ti = 0, tj = 0;
                if (T >= 16) {
                    tbm = t / (MT * MT);
                    int rem = t % (MT * MT);
                    ti = rem / MT;
                    tj = rem % MT;
                }
                int fr = lane >> 2, fc = (lane & 3) * 2;
#pragma unroll
                for (int j = 0; j < 2; j++)
#pragma unroll
                    for (int q = 0; q < 4; q++) {
                        int rr = fr + (q >> 1) * 8;
                        int cc = fc + (q & 1) + j * 8;
                        float v = sfr[slot][j][q];
                        if (T < 16) {
                            int qr = rr / T, qc = cc / T;
                            if (qr == qc && qr < QB) {
                                int bm = t * QB + qr;
                                if (bm < nbm) sS[(bm * T + rr - qr * T) * TCS + (cc - qc * T)] = v;
                            }
                        } else {
                            if (tbm < nbm && ti * 16 + rr < T && tj * 16 + cc < T)
                                sS[(tbm * T + ti * 16 + rr) * TCS + tj * 16 + cc] = v;
                        }
                    }
            }
        }
        __syncthreads();

        float cterm = g_cc[layer];
        const float* zu = (const float*)(smem + OZU) + layer * 128;
        const float* zv = (const float*)(smem + OZV) + layer * 128;
        int e = lane;
        for (int rho = wid; rho < nrows; rho += 16) {
            int bm = rho / T, l = rho % T;
            const float* row = sS + (bm * T + l) * TCS;
            bool v0 = (e < T);
            bool v1 = (T > 32) && (e + 32 < T);
            float zul = zu[rho];
            float x0 = v0 ? SCALE * (row[e] + zul + zv[bm * T + e] + cterm) : -1e30f;
            float x1 = v1 ? SCALE * (row[e + 32] + zul + zv[bm * T + e + 32] + cterm) : -1e30f;
            float mx = fmaxf(x0, x1);
#pragma unroll
            for (int o = 16; o; o >>= 1) mx = fmaxf(mx, __shfl_xor_sync(0xffffffffu, mx, o));
            float e0 = v0 ? __expf(x0 - mx) : 0.f;
            float e1 = v1 ? __expf(x1 - mx) : 0.f;
            float ssum = e0 + e1;
#pragma unroll
            for (int o = 16; o; o >>= 1) ssum += __shfl_xor_sync(0xffffffffu, ssum, o);
            float inv = 1.0f / ssum;
            __half* So = g_S + soff + ((size_t)layer * BM + bm0 + bm) * T * T + (size_t)l * T;
            if (v0) So[e] = __float2half_rn(e0 * inv);
            if (v1) So[e + 32] = __float2half_rn(e1 * inv);
        }
    }
#undef STAGE_B
}

// ---------------- mega fused kernel: all 6 branches in one grid ----------------
__global__ __launch_bounds__(512, 1) void mega_fused_kernel() {
    extern __shared__ __align__(128) char smem[];
    int blk = blockIdx.x;
    if (blk < 2347) {
        fused_body<35, 3>(smem, 0, 0, blk * 3, SOFF0);
    } else if (blk < 2523) {
        fused_body<3, 35>(smem, 1, 35, (blk - 2347) * 40, SOFF1);
    } else if (blk < 3697) {
        fused_body<21, 5>(smem, 2, 38, (blk - 2523) * 6, SOFF2);
    } else if (blk < 3991) {
        fused_body<5, 21>(smem, 3, 59, (blk - 3697) * 24, SOFF3);
    } else if (blk < 4871) {
        fused_body<15, 7>(smem, 4, 64, (blk - 3991) * 8, SOFF4);
    } else {
        fused_body<7, 15>(smem, 5, 79, (blk - 4871) * 16, SOFF5);
    }
}

// ---------------- channel mean + expand (one mega launch) ----------------
template <int T, int P, bool TILE>
__device__ __forceinline__ void mean_expand_body(float* __restrict__ out, int b, int layer, size_t soff) {
    constexpr int TT = T * T;
    __shared__ float sA[35 * 35];
    __shared__ short alT[LN], asT[LN];
    const __half* Sb = g_S + soff + ((size_t)layer * BM + (size_t)b * MN) * TT;
    for (int r = threadIdx.x; r < TT; r += 256) {
        float s = 0.f;
#pragma unroll 5
        for (int m = 0; m < MN; m++) s += __half2float(Sb[(size_t)m * TT + r]);
        sA[r] = s * (1.0f / MN);
    }
    if (threadIdx.x < LN) {
        int i = threadIdx.x;
        alT[i] = (short)((TILE ? (i % P) : (i / P)) * T);
        asT[i] = (short)(TILE ? (i % P) : (i / P));
    }
    __syncthreads();
    float* ob = out + ((size_t)layer * BN + b) * LL;
    for (int i = threadIdx.x; i < LL; i += 256) {
        int l = i / LN, s = i - l * LN;
        ob[i] = sA[alT[l] + asT[s]];
    }
}

__global__ __launch_bounds__(256) void mega_mean_kernel(float* __restrict__ out) {
    int blk = blockIdx.x;
    int seg = blk / 384;
    int rem = blk % 384;
    int b = rem & 127, layer = rem >> 7;
    switch (seg) {
        case 0: mean_expand_body<35, 3, false>(out + (size_t)0 * BN * LL, b, layer, SOFF0); break;
        case 1: mean_expand_body<3, 3, true>(out + (size_t)9 * BN * LL, b, layer, SOFF1); break;
        case 2: mean_expand_body<21, 5, false>(out + (size_t)3 * BN * LL, b, layer, SOFF2); break;
        case 3: mean_expand_body<5, 5, true>(out + (size_t)12 * BN * LL, b, layer, SOFF3); break;
        case 4: mean_expand_body<15, 7, false>(out + (size_t)6 * BN * LL, b, layer, SOFF4); break;
        default: mean_expand_body<7, 7, true>(out + (size_t)15 * BN * LL, b, layer, SOFF5); break;
    }
}

extern "C" void kernel_launch(void* const* d_in, const int* in_sizes, int n_in,
                              void* d_out, int out_size) {
    const float* x = (const float*)d_in[0];
    const float* Wq = (const float*)d_in[7];
    const float* bq = (const float*)d_in[8];
    const float* Wk = (const float*)d_in[9];
    const float* bk = (const float*)d_in[10];
    float* out = (float*)d_out;

    cudaFuncSetAttribute(mega_fused_kernel, cudaFuncAttributeMaxDynamicSharedMemorySize, FUSED_SMEM);

    k1_kernel<<<2614, 256>>>(x, Wq, Wk, bq, bk,
                             (const float*)d_in[1], (const float*)d_in[2],
                             (const float*)d_in[3], (const float*)d_in[4],
                             (const float*)d_in[5], (const float*)d_in[6]);
    mega_fused_kernel<<<5311, 512, FUSED_SMEM>>>();
    mega_mean_kernel<<<2304, 256>>>(out);
}

// round 17
// speedup vs baseline: 2.3886x; 1.6699x over previous
#include <cuda_runtime.h>
#include <cuda_fp16.h>
#include <math.h>
#include <cstdint>

#define BN 128
#define LN 105
#define MN 55
#define DN 256
#define ELN 3
static constexpr int BM = BN * MN;      // 7040
static constexpr int LL = LN * LN;      // 11025
static constexpr float SCALE = 0.0625f; // 1/sqrt(256)

// per-branch g_S offsets (halves)
static constexpr size_t SOFF0 = 0;
static constexpr size_t SOFF1 = (size_t)3 * BM * 1225;
static constexpr size_t SOFF2 = (size_t)3 * BM * 1234;
static constexpr size_t SOFF3 = (size_t)3 * BM * 1675;
static constexpr size_t SOFF4 = (size_t)3 * BM * 1700;
static constexpr size_t SOFF5 = (size_t)3 * BM * 1925;
static constexpr size_t STOT  = (size_t)3 * BM * 1974;

// E row bookkeeping: KP = {48,112,48,80,48,64}, cum = {0,48,160,208,288,336}, tot 400
// ---------------- scratch (device globals) ----------------
__device__ __align__(128) float g_xt[BM * LN];
__device__ __align__(128) float g_meff[ELN * DN * DN];       // fp32 Meff
__device__ __align__(128) float g_E[400 * DN];               // Etilde rows (zero padded)
__device__ __align__(128) float g_FT[3 * 400 * DN];          // F^T per (l,br): [256][KP]
__device__ __align__(128) __half g_ahat[18 * 128 * 128];     // Ahat^T: [pair][n][k] fp16
__device__ float g_u[ELN * DN];
__device__ float g_v[ELN * DN];
__device__ float g_cc[ELN];
__device__ float g_ut[18 * 128];                             // Etilde @ u (zero padded)
__device__ float g_vt[18 * 128];
__device__ __align__(128) __half g_S[STOT];

// ---------------- helpers ----------------
__device__ __forceinline__ uint32_t smem_u32(const void* p) {
    uint32_t a;
    asm("{ .reg .u64 t; cvta.to.shared.u64 t, %1; cvt.u32.u64 %0, t; }" : "=r"(a) : "l"(p));
    return a;
}
__device__ __forceinline__ void cp_async16(uint32_t saddr, const void* gptr) {
    asm volatile("cp.async.ca.shared.global [%0], [%1], 16;" :: "r"(saddr), "l"(gptr) : "memory");
}
__device__ __forceinline__ void mma16816(float* d, const uint32_t* a, uint32_t b0, uint32_t b1) {
    asm volatile(
        "mma.sync.aligned.m16n8k16.row.col.f32.f16.f16.f32 "
        "{%0,%1,%2,%3}, {%4,%5,%6,%7}, {%8,%9}, {%0,%1,%2,%3};"
        : "+f"(d[0]), "+f"(d[1]), "+f"(d[2]), "+f"(d[3])
        : "r"(a[0]), "r"(a[1]), "r"(a[2]), "r"(a[3]), "r"(b0), "r"(b1));
}
#define LDMX4(r0, r1, r2, r3, addr) \
    asm volatile("ldmatrix.sync.aligned.m8n8.x4.shared.b16 {%0,%1,%2,%3}, [%4];" \
        : "=r"(r0), "=r"(r1), "=r"(r2), "=r"(r3) : "r"(addr))

__constant__ int c_T[6] = {35, 3, 21, 5, 15, 7};
__constant__ int c_C[6] = {3, 35, 5, 21, 7, 15};
__constant__ int c_KP[6] = {48, 112, 48, 80, 48, 64};
__constant__ int c_cum[7] = {0, 48, 160, 208, 288, 336, 400};

// ---------------- K1: revin + meff(fp32) + uvc + Etilde build ----------------
__global__ __launch_bounds__(256) void k1_kernel(
    const float* __restrict__ x,
    const float* __restrict__ Wq, const float* __restrict__ Wk,
    const float* __restrict__ bq, const float* __restrict__ bk,
    const float* __restrict__ w0, const float* __restrict__ w1,
    const float* __restrict__ w2, const float* __restrict__ w3,
    const float* __restrict__ w4, const float* __restrict__ w5) {
    int blk = blockIdx.x;
    int tid = threadIdx.x;
    if (blk < 128) {
        __shared__ float sx[LN * MN];
        __shared__ float smean[MN], sinv[MN];
        int b = blk;
        const float* xb = x + (size_t)b * LN * MN;
        for (int i = tid; i < LN * MN; i += 256) sx[i] = xb[i];
        __syncthreads();
        for (int m = tid; m < MN; m += 256) {
            float s = 0.f, s2 = 0.f;
            for (int l = 0; l < LN; l++) { float v = sx[l * MN + m]; s += v; s2 += v * v; }
            float mean = s * (1.0f / LN);
            float var = s2 * (1.0f / LN) - mean * mean;
            smean[m] = mean;
            sinv[m] = rsqrtf(var + 1e-5f);
        }
        __syncthreads();
        float* ob = g_xt + (size_t)b * MN * LN;
        for (int i = tid; i < MN * LN; i += 256) {
            int m = i / LN, l = i - m * LN;
            ob[i] = (sx[l * MN + m] - smean[m]) * sinv[m];
        }
    } else if (blk < 896) {
        // meff[l][i][j] = Wq_row(i) . Wk_row(j)   (fp32)
        __shared__ float sq[16][17], sk[16][17];
        int u = blk - 128;
        int l = u >> 8;
        int rem = u & 255;
        int i0 = (rem >> 4) * 16, j0 = (rem & 15) * 16;
        int ty = tid >> 4, tx = tid & 15;
        float acc = 0.f;
        const float* wq = Wq + (size_t)l * DN * DN;
        const float* wk = Wk + (size_t)l * DN * DN;
        for (int k0 = 0; k0 < DN; k0 += 16) {
            sq[ty][tx] = wq[(i0 + ty) * DN + k0 + tx];
            sk[ty][tx] = wk[(j0 + ty) * DN + k0 + tx];
            __syncthreads();
#pragma unroll
            for (int kk = 0; kk < 16; kk++) acc += sq[ty][kk] * sk[tx][kk];
            __syncthreads();
        }
        g_meff[(size_t)l * DN * DN + (i0 + ty) * DN + j0 + tx] = acc;
    } else if (blk < 992) {
        int u = blk - 896;
        int l = u >> 5, r = u & 31;
        int wid = tid >> 5, lane = tid & 31;
        int k = r * 8 + wid;
        float su = 0.f, sv = 0.f;
        const float* wq = Wq + (size_t)l * DN * DN + (size_t)k * DN;
        const float* wk = Wk + (size_t)l * DN * DN + (size_t)k * DN;
        for (int d = lane; d < DN; d += 32) {
            su += wq[d] * bk[l * DN + d];
            sv += wk[d] * bq[l * DN + d];
        }
#pragma unroll
        for (int o = 16; o; o >>= 1) {
            su += __shfl_xor_sync(0xffffffffu, su, o);
            sv += __shfl_xor_sync(0xffffffffu, sv, o);
        }
        if (lane == 0) {
            g_u[l * DN + k] = su;
            g_v[l * DN + k] = sv;
        }
        if (r == 0 && wid == 0) {
            float c = 0.f;
            for (int d = lane; d < DN; d += 32) c += bq[l * DN + d] * bk[l * DN + d];
#pragma unroll
            for (int o = 16; o; o >>= 1) c += __shfl_xor_sync(0xffffffffu, c, o);
            if (lane == 0) g_cc[l] = c;
        }
    } else {
        // ---- Etilde build: row = blk-992 in 0..399 ----
        int row = blk - 992;
        int br = 0;
#pragma unroll
        for (int q = 1; q < 6; q++)
            if (row >= c_cum[q]) br = q;
        int kl = row - c_cum[br];
        int C = c_C[br], T = c_T[br];
        int d = tid;
        float v = 0.f;
        if (kl < 3 * C) {
            const float* wp = br == 0 ? w0 : br == 1 ? w1 : br == 2 ? w2 : br == 3 ? w3 : br == 4 ? w4 : w5;
            v = wp[d * 3 * C + kl];
        } else if (kl < 3 * C + T) {
            int t = kl - 3 * C;
            float freq = expf(-(float)(2 * (d >> 1)) * (9.210340371976184f / 256.f));
            float arg = (float)t * freq;
            v = (d & 1) ? cosf(arg) : sinf(arg);
        }
        g_E[row * DN + d] = v;
    }
}

// ---------------- K2: F = E @ M (store F^T), plus ut/vt ----------------
__global__ __launch_bounds__(256) void k2_kernel() {
    __shared__ float se[256];
    __shared__ float su[256], sv[256];
    int blk = blockIdx.x;            // 1200 = 3 layers * 400 rows
    int l = blk / 400;
    int row = blk % 400;
    int br = 0;
#pragma unroll
    for (int q = 1; q < 6; q++)
        if (row >= c_cum[q]) br = q;
    int k = row - c_cum[br];
    int KP = c_KP[br];
    int tid = threadIdx.x;
    float e = g_E[row * DN + tid];
    se[tid] = e;
    su[tid] = e * g_u[l * DN + tid];
    sv[tid] = e * g_v[l * DN + tid];
    __syncthreads();
    for (int s = 128; s; s >>= 1) {
        if (tid < s) {
            su[tid] += su[tid + s];
            sv[tid] += sv[tid + s];
        }
        __syncthreads();
    }
    if (tid == 0 && k < 128) {
        g_ut[(br * 3 + l) * 128 + k] = su[0];
        g_vt[(br * 3 + l) * 128 + k] = sv[0];
    }
    float acc = 0.f;
    const float* M = g_meff + (size_t)l * DN * DN;
    for (int i = 0; i < 256; i++) acc += se[i] * M[(size_t)i * DN + tid];
    g_FT[(size_t)(l * 400 + c_cum[br]) * DN + (size_t)tid * KP + k] = acc;
}

// ---------------- K3: Ahat^T[n][k] = F[k] . E[n] ----------------
__global__ __launch_bounds__(128) void k3_kernel() {
    __shared__ float se[256];
    int blk = blockIdx.x;            // 2304 = 18 pairs * 128 n-rows
    int pair = blk >> 7;
    int n = blk & 127;
    int br = pair / 3, l = pair % 3;
    int KP = c_KP[br];
    int tid = threadIdx.x;
    __half* dst = g_ahat + (size_t)pair * 16384 + (size_t)n * 128;
    if (n >= KP) {
        dst[tid] = __float2half_rn(0.f);
        return;
    }
    se[tid] = g_E[(c_cum[br] + n) * DN + tid];
    se[tid + 128] = g_E[(c_cum[br] + n) * DN + tid + 128];
    __syncthreads();
    float acc = 0.f;
    if (tid < KP) {
        const float* FT = g_FT + (size_t)(l * 400 + c_cum[br]) * DN;
        for (int j = 0; j < 256; j++) acc += se[j] * FT[(size_t)j * KP + tid];
    }
    dst[tid] = __float2half_rn(acc);
}

// ---------------- fused body ----------------
static constexpr int OXT = 0;        // Xtilde [128][128] fp16 (32768)
static constexpr int OP  = 32768;    // P [128][128] fp16 (32768)
static constexpr int OA  = 65536;    // Ahat staged [128][128] fp16 (32768); sS overlays
static constexpr int OSS = 65536;
static constexpr int OU  = 98304;    // ut [3][128] f32 (1536)
static constexpr int OV  = 99840;
static constexpr int OZU = 101376;
static constexpr int OZV = 102912;
static constexpr int FUSED_SMEM = 104448;

template <int T, int C>
__device__ __forceinline__ void fused_body(char* smem, int br, int bm0, size_t soff) {
    constexpr int MT = (T + 15) / 16;
    constexpr int QB = (T < 16) ? (16 / T) : 1;
    constexpr int NB = (T < 16) ? (8 * QB) : (128 / T);
    constexpr int NTILES = (T < 16) ? 8 : (NB * MT * MT);
    constexpr int TC = (T + 3) & ~3;
    constexpr int TCS = TC + 1;
    constexpr int SLOTS = (NTILES + 15) / 16;
    constexpr int K3 = 3 * C + T;
    constexpr int KP = (K3 + 15) & ~15;
    constexpr int KS = KP / 16;
    constexpr int JBMAX = (KS + 1) / 2;

    const uint32_t sb = smem_u32(smem);
    const int tid = threadIdx.x;
    const int lane = tid & 31;
    const int wid = tid >> 5;
    const int nbm = min(NB, BM - bm0);
    const int nrows = nbm * T;

    const int rA = lane & 15;
    const int chsel = lane >> 4;
    const int wm8 = wid >> 1, wn2 = wid & 1;

    // ---- stage ut/vt for all 3 layers ----
    for (int i = tid; i < 384; i += 512) {
        ((float*)(smem + OU))[i] = g_ut[(br * 3) * 128 + i];
        ((float*)(smem + OV))[i] = g_vt[(br * 3) * 128 + i];
    }

    // ---- build Xtilde [128][128]: window | one-hot | zeros ----
    for (int i = tid; i < 128 * 128; i += 512) {
        int r = i >> 7, k = i & 127;
        float v = 0.f;
        if (r < nrows) {
            int bmi = r / T, t = r - bmi * T;
            if (k < 3 * C) {
                int c = k / 3, j = k - c * 3;
                int ts = t + j - 1;
                ts = (ts < 0) ? ts + T : (ts >= T ? ts - T : ts);
                v = __ldg(&g_xt[(size_t)(bm0 + bmi) * LN + ts * C + c]);
            } else if (k < K3) {
                v = (k - 3 * C == t) ? 1.f : 0.f;
            }
        }
        uint32_t off = r * 256 + (((k >> 3) ^ (r & 7)) << 4) + (k & 7) * 2;
        *(__half*)(smem + OXT + off) = __float2half_rn(v);
    }
    __syncthreads();

    // ---- zu/zv per row for ALL 3 layers (4 threads per row, 128 cols) ----
    {
        int r = tid >> 2, p = tid & 3;
        float au[3] = {0.f, 0.f, 0.f}, av[3] = {0.f, 0.f, 0.f};
        if (r < nrows) {
            const float4* su4 = (const float4*)(smem + OU);
            const float4* sv4 = (const float4*)(smem + OV);
            for (int c = p * 4; c < p * 4 + 4; c++) {
                uint32_t off = r * 256 + ((c ^ (r & 7)) << 4);
                uint4 zz = *(const uint4*)(smem + OXT + off);
                const __half2* hz = (const __half2*)&zz;
                float2 z0 = __half22float2(hz[0]);
                float2 z1 = __half22float2(hz[1]);
                float2 z2 = __half22float2(hz[2]);
                float2 z3 = __half22float2(hz[3]);
#pragma unroll
                for (int l = 0; l < 3; l++) {
                    int base = (l * 128 + c * 8) >> 2;
                    float4 ua = su4[base], ub = su4[base + 1];
                    float4 va = sv4[base], vb = sv4[base + 1];
                    au[l] += z0.x * ua.x + z0.y * ua.y + z1.x * ua.z + z1.y * ua.w +
                             z2.x * ub.x + z2.y * ub.y + z3.x * ub.z + z3.y * ub.w;
                    av[l] += z0.x * va.x + z0.y * va.y + z1.x * va.z + z1.y * va.w +
                             z2.x * vb.x + z2.y * vb.y + z3.x * vb.z + z3.y * vb.w;
                }
            }
        }
#pragma unroll
        for (int l = 0; l < 3; l++) {
            au[l] += __shfl_xor_sync(0xffffffffu, au[l], 1);
            au[l] += __shfl_xor_sync(0xffffffffu, au[l], 2);
            av[l] += __shfl_xor_sync(0xffffffffu, av[l], 1);
            av[l] += __shfl_xor_sync(0xffffffffu, av[l], 2);
        }
        if (p == 0 && r < nrows) {
#pragma unroll
            for (int l = 0; l < 3; l++) {
                ((float*)(smem + OZU))[l * 128 + r] = au[l];
                ((float*)(smem + OZV))[l * 128 + r] = av[l];
            }
        }
    }

    for (int layer = 0; layer < ELN; layer++) {
        __syncthreads();   // prior layer's softmax done reading sS (OA overlay)

        // ---- stage Ahat^T for this layer ----
        {
            const __half* Asrc = g_ahat + (size_t)(br * 3 + layer) * 16384;
#pragma unroll
            for (int it = 0; it < 4; it++) {
                int idx = it * 512 + tid;
                int row = idx >> 4, chk = idx & 15;
                uint32_t off = row * 256 + ((chk ^ (row & 7)) << 4);
                cp_async16(sb + OA + off, Asrc + (size_t)row * 128 + chk * 8);
            }
            asm volatile("cp.async.commit_group;" ::: "memory");
        }
        asm volatile("cp.async.wait_group 0;" ::: "memory");
        __syncthreads();

        // ---- phase1: P = Xtilde @ Ahat  (m16 per warp, n split by parity) ----
        {
            float acc[JBMAX][8];
#pragma unroll
            for (int a = 0; a < JBMAX; a++)
#pragma unroll
                for (int q = 0; q < 8; q++) acc[a][q] = 0.f;

#pragma unroll
            for (int kstep = 0; kstep < KS; kstep++) {
                int arow = wm8 * 16 + rA;
                uint32_t aad = sb + OXT + arow * 256 + (((kstep * 2 + chsel) ^ (arow & 7)) << 4);
                uint32_t a[4];
                LDMX4(a[0], a[1], a[2], a[3], aad);
                int jbi = 0;
#pragma unroll
                for (int jb = 0; jb < KS; jb++) {
                    if ((jb & 1) != wn2) continue;
                    int brow = jb * 16 + rA;
                    uint32_t bad = sb + OA + brow * 256 + (((kstep * 2 + chsel) ^ (brow & 7)) << 4);
                    uint32_t b0, b1, b2, b3;
                    LDMX4(b0, b1, b2, b3, bad);
                    mma16816(acc[jbi] + 0, a, b0, b2);
                    mma16816(acc[jbi] + 4, a, b1, b3);
                    jbi++;
                }
            }
            // P write (fp16, stride 256B)
            int jbi = 0;
#pragma unroll
            for (int jb = 0; jb < KS; jb++) {
                if ((jb & 1) != wn2) continue;
#pragma unroll
                for (int ng = 0; ng < 2; ng++)
#pragma unroll
                    for (int half = 0; half < 2; half++) {
                        int r = wm8 * 16 + (lane >> 2) + half * 8;
                        int c = jb * 16 + ng * 8 + (lane & 3) * 2;
                        float v0 = acc[jbi][ng * 4 + half * 2 + 0];
                        float v1 = acc[jbi][ng * 4 + half * 2 + 1];
                        uint32_t off = r * 256 + (((c >> 3) ^ (r & 7)) << 4) + (c & 7) * 2;
                        *(__half2*)(smem + OP + off) = __half2(__float2half_rn(v0), __float2half_rn(v1));
                    }
                jbi++;
            }
        }
        __syncthreads();

        // ---- phase2: S = P @ Xtilde^T on diagonal tiles ----
        float sfr[SLOTS][2][4];
#pragma unroll
        for (int s = 0; s < SLOTS; s++)
#pragma unroll
            for (int j = 0; j < 2; j++)
#pragma unroll
                for (int q = 0; q < 4; q++) sfr[s][j][q] = 0.f;

        {
            int slot = 0;
            for (int t = wid; t < NTILES; t += 16, slot++) {
                int rb, cb;
                if (T < 16) {
                    rb = cb = t * QB * T;
                } else {
                    int tbm = t / (MT * MT);
                    int rem = t % (MT * MT);
                    rb = tbm * T + (rem / MT) * 16;
                    cb = tbm * T + (rem % MT) * 16;
                }
#pragma unroll
                for (int kc = 0; kc < KS; kc++) {
                    int ch = kc * 2 + chsel;
                    int arow = rb + rA;
                    uint32_t aad = sb + OP + arow * 256 + ((ch ^ (arow & 7)) << 4);
                    uint32_t gh[4];
                    LDMX4(gh[0], gh[1], gh[2], gh[3], aad);
                    int brow = cb + rA;
                    uint32_t bad = sb + OXT + brow * 256 + ((ch ^ (brow & 7)) << 4);
                    uint32_t zh[4];
                    LDMX4(zh[0], zh[1], zh[2], zh[3], bad);
                    mma16816(sfr[slot][0], gh, zh[0], zh[2]);
                    mma16816(sfr[slot][1], gh, zh[1], zh[3]);
                }
            }
        }
        __syncthreads();   // phase1 OA reads done (already), P reads done before sS write? P read in phase2 above; sS in OA region - ok

        // ---- S frags -> smem overlay (OA region) ----
        float* sS = (float*)(smem + OSS);
        {
            int slot = 0;
            for (int t = wid; t < NTILES; t += 16, slot++) {
                int tbm = -1, ti = 0, tj = 0;
                if (T >= 16) {
                    tbm = t / (MT * MT);
                    int rem = t % (MT * MT);
                    ti = rem / MT;
                    tj = rem % MT;
                }
                int fr = lane >> 2, fc = (lane & 3) * 2;
#pragma unroll
                for (int j = 0; j < 2; j++)
#pragma unroll
                    for (int q = 0; q < 4; q++) {
                        int rr = fr + (q >> 1) * 8;
                        int cc = fc + (q & 1) + j * 8;
                        float v = sfr[slot][j][q];
                        if (T < 16) {
                            int qr = rr / T, qc = cc / T;
                            if (qr == qc && qr < QB) {
                                int bm = t * QB + qr;
                                if (bm < nbm) sS[(bm * T + rr - qr * T) * TCS + (cc - qc * T)] = v;
                            }
                        } else {
                            if (tbm < nbm && ti * 16 + rr < T && tj * 16 + cc < T)
                                sS[(tbm * T + ti * 16 + rr) * TCS + tj * 16 + cc] = v;
                        }
                    }
            }
        }
        __syncthreads();

        // ---- softmax rows -> g_S (fp16) ----
        float cterm = g_cc[layer];
        const float* zu = (const float*)(smem + OZU) + layer * 128;
        const float* zv = (const float*)(smem + OZV) + layer * 128;
        int e = lane;
        for (int rho = wid; rho < nrows; rho += 16) {
            int bm = rho / T, l = rho % T;
            const float* row = sS + (bm * T + l) * TCS;
            bool v0 = (e < T);
            bool v1 = (T > 32) && (e + 32 < T);
            float zul = zu[rho];
            float x0 = v0 ? SCALE * (row[e] + zul + zv[bm * T + e] + cterm) : -1e30f;
            float x1 = v1 ? SCALE * (row[e + 32] + zul + zv[bm * T + e + 32] + cterm) : -1e30f;
            float mx = fmaxf(x0, x1);
#pragma unroll
            for (int o = 16; o; o >>= 1) mx = fmaxf(mx, __shfl_xor_sync(0xffffffffu, mx, o));
            float e0 = v0 ? __expf(x0 - mx) : 0.f;
            float e1 = v1 ? __expf(x1 - mx) : 0.f;
            float ssum = e0 + e1;
#pragma unroll
            for (int o = 16; o; o >>= 1) ssum += __shfl_xor_sync(0xffffffffu, ssum, o);
            float inv = 1.0f / ssum;
            __half* So = g_S + soff + ((size_t)layer * BM + bm0 + bm) * T * T + (size_t)l * T;
            if (v0) So[e] = __float2half_rn(e0 * inv);
            if (v1) So[e + 32] = __float2half_rn(e1 * inv);
        }
    }
}

// ---------------- mega fused kernel ----------------
__global__ __launch_bounds__(512, 1) void mega_fused_kernel() {
    extern __shared__ __align__(128) char smem[];
    int blk = blockIdx.x;
    if (blk < 2347) {
        fused_body<35, 3>(smem, 0, blk * 3, SOFF0);
    } else if (blk < 2523) {
        fused_body<3, 35>(smem, 1, (blk - 2347) * 40, SOFF1);
    } else if (blk < 3697) {
        fused_body<21, 5>(smem, 2, (blk - 2523) * 6, SOFF2);
    } else if (blk < 3991) {
        fused_body<5, 21>(smem, 3, (blk - 3697) * 24, SOFF3);
    } else if (blk < 4871) {
        fused_body<15, 7>(smem, 4, (blk - 3991) * 8, SOFF4);
    } else {
        fused_body<7, 15>(smem, 5, (blk - 4871) * 16, SOFF5);
    }
}

// ---------------- channel mean + expand (one mega launch) ----------------
template <int T, int P, bool TILE>
__device__ __forceinline__ void mean_expand_body(float* __restrict__ out, int b, int layer, size_t soff) {
    constexpr int TT = T * T;
    __shared__ float sA[35 * 35];
    __shared__ short alT[LN], asT[LN];
    const __half* Sb = g_S + soff + ((size_t)layer * BM + (size_t)b * MN) * TT;
    for (int r = threadIdx.x; r < TT; r += 256) {
        float s = 0.f;
#pragma unroll 5
        for (int m = 0; m < MN; m++) s += __half2float(Sb[(size_t)m * TT + r]);
        sA[r] = s * (1.0f / MN);
    }
    if (threadIdx.x < LN) {
        int i = threadIdx.x;
        alT[i] = (short)((TILE ? (i % P) : (i / P)) * T);
        asT[i] = (short)(TILE ? (i % P) : (i / P));
    }
    __syncthreads();
    float* ob = out + ((size_t)layer * BN + b) * LL;
    for (int i = threadIdx.x; i < LL; i += 256) {
        int l = i / LN, s = i - l * LN;
        ob[i] = sA[alT[l] + asT[s]];
    }
}

__global__ __launch_bounds__(256) void mega_mean_kernel(float* __restrict__ out) {
    int blk = blockIdx.x;
    int seg = blk / 384;
    int rem = blk % 384;
    int b = rem & 127, layer = rem >> 7;
    switch (seg) {
        case 0: mean_expand_body<35, 3, false>(out + (size_t)0 * BN * LL, b, layer, SOFF0); break;
        case 1: mean_expand_body<3, 3, true>(out + (size_t)9 * BN * LL, b, layer, SOFF1); break;
        case 2: mean_expand_body<21, 5, false>(out + (size_t)3 * BN * LL, b, layer, SOFF2); break;
        case 3: mean_expand_body<5, 5, true>(out + (size_t)12 * BN * LL, b, layer, SOFF3); break;
        case 4: mean_expand_body<15, 7, false>(out + (size_t)6 * BN * LL, b, layer, SOFF4); break;
        default: mean_expand_body<7, 7, true>(out + (size_t)15 * BN * LL, b, layer, SOFF5); break;
    }
}

extern "C" void kernel_launch(void* const* d_in, const int* in_sizes, int n_in,
                              void* d_out, int out_size) {
    const float* x = (const float*)d_in[0];
    const float* Wq = (const float*)d_in[7];
    const float* bq = (const float*)d_in[8];
    const float* Wk = (const float*)d_in[9];
    const float* bk = (const float*)d_in[10];
    float* out = (float*)d_out;

    cudaFuncSetAttribute(mega_fused_kernel, cudaFuncAttributeMaxDynamicSharedMemorySize, FUSED_SMEM);

    k1_kernel<<<1392, 256>>>(x, Wq, Wk, bq, bk,
                             (const float*)d_in[1], (const float*)d_in[2],
                             (const float*)d_in[3], (const float*)d_in[4],
                             (const float*)d_in[5], (const float*)d_in[6]);
    k2_kernel<<<1200, 256>>>();
    k3_kernel<<<2304, 128>>>();
    mega_fused_kernel<<<5311, 512, FUSED_SMEM>>>();
    mega_mean_kernel<<<2304, 256>>>(out);
}